// round 15
// baseline (speedup 1.0000x reference)
#include <cuda_runtime.h>
#include <cuda_bf16.h>

#define NB 8
#define SEQ 1024
#define SFULL 1025
#define EMB 768
#define NH 12
#define HD 64
#define BH (NB*NH)   // 96
#define MOUT (NB*SFULL) // 8200

typedef unsigned u32;
typedef __nv_bfloat16 bf16;
typedef __nv_bfloat162 bf162;

// ---------------- static scratch ----------------
__device__ float g_C[NB*EMB];
__device__ float g_coef[BH*SEQ];
__device__ float g_ck[BH*SEQ];

__device__ bf16 g_xh[NB*SFULL*EMB], g_xl[NB*SFULL*EMB];
__device__ bf16 g_Wqh[EMB*EMB], g_Wql[EMB*EMB];
__device__ bf16 g_Wkh[EMB*EMB], g_Wkl[EMB*EMB];
__device__ bf16 g_Wvh[EMB*EMB], g_Wvl[EMB*EMB];
__device__ bf16 g_Woh[EMB*EMB], g_Wol[EMB*EMB];
__device__ bf16 g_Qh[NB*SEQ*EMB], g_Ql[NB*SEQ*EMB];
__device__ bf16 g_Kh[NB*SEQ*EMB], g_Kl[NB*SEQ*EMB];
__device__ bf16 g_Vh[NB*SEQ*EMB], g_Vl[NB*SEQ*EMB];
__device__ bf16 g_Yh[NB*SFULL*EMB], g_Yl[NB*SFULL*EMB];

// ---------------- helpers ----------------
__device__ __forceinline__ void mma_bf16(float* d, const u32* a, const u32* b) {
    asm("mma.sync.aligned.m16n8k16.row.col.f32.bf16.bf16.f32 "
        "{%0,%1,%2,%3},{%4,%5,%6,%7},{%8,%9},{%0,%1,%2,%3};"
        : "+f"(d[0]), "+f"(d[1]), "+f"(d[2]), "+f"(d[3])
        : "r"(a[0]), "r"(a[1]), "r"(a[2]), "r"(a[3]), "r"(b[0]), "r"(b[1]));
}
__device__ __forceinline__ void ldsm4(u32& r0,u32& r1,u32& r2,u32& r3, u32 addr){
    asm volatile("ldmatrix.sync.aligned.m8n8.x4.shared.b16 {%0,%1,%2,%3},[%4];"
        : "=r"(r0),"=r"(r1),"=r"(r2),"=r"(r3) : "r"(addr));
}
__device__ __forceinline__ void ldsm4t(u32& r0,u32& r1,u32& r2,u32& r3, u32 addr){
    asm volatile("ldmatrix.sync.aligned.m8n8.x4.trans.shared.b16 {%0,%1,%2,%3},[%4];"
        : "=r"(r0),"=r"(r1),"=r"(r2),"=r"(r3) : "r"(addr));
}
__device__ __forceinline__ u32 sptr(const void* p){
    return (u32)__cvta_generic_to_shared(p);
}
__device__ __forceinline__ void cpa16(u32 saddr, const void* g){
    asm volatile("cp.async.cg.shared.global [%0],[%1],16;" :: "r"(saddr), "l"(g));
}
__device__ __forceinline__ void cpa_commit(){
    asm volatile("cp.async.commit_group;");
}
template<int N>
__device__ __forceinline__ void cpa_wait(){
    asm volatile("cp.async.wait_group %0;" :: "n"(N));
}
// swizzled smem index (stride 24 bf16/row, XOR 8-col halves by row bit3)
__device__ __forceinline__ int sx(int r, int c) { return r*24 + (c ^ (((r>>3)&1)<<3)); }

__device__ __forceinline__ void split1(float v, bf16& h, bf16& l) {
    h = __float2bfloat16(v);
    l = __float2bfloat16(v - __bfloat162float(h));
}
__device__ __forceinline__ void split8(const float* v, uint4& H, uint4& L) {
    bf16 hh[8], ll[8];
#pragma unroll
    for (int e = 0; e < 8; e++) split1(v[e], hh[e], ll[e]);
    H = *(uint4*)hh; L = *(uint4*)ll;
}

template<int MT>
__device__ __forceinline__ void load_afrag(u32 Ah[][4], u32 Al[][4],
                                           u32 baseh, u32 basel, int rbase, int lane)
{
    int r = rbase + (lane & 15);
    int kc = (lane >> 4) << 3;
#pragma unroll
    for (int i = 0; i < MT; i++) {
        u32 off = 2u * sx(r + 16*i, kc);
        ldsm4(Ah[i][0],Ah[i][1],Ah[i][2],Ah[i][3], baseh + off);
        ldsm4(Al[i][0],Al[i][1],Al[i][2],Al[i][3], basel + off);
    }
}

template<int MT, int NT>
__device__ __forceinline__ void mma_block(
    float acc[MT][NT][4], const u32 Ah[][4], const u32 Al[][4],
    u32 bbh, u32 bbl, int cbase, int lane)
{
    int nrow = (lane & 7) + ((lane >> 4) << 3);
    int kc = ((lane >> 3) & 1) << 3;
#pragma unroll
    for (int jp = 0; jp < NT/2; jp++) {
        u32 off = 2u * sx(cbase + 16*jp + nrow, kc);
        u32 bh[4], bl[4];
        ldsm4(bh[0],bh[1],bh[2],bh[3], bbh + off);
        ldsm4(bl[0],bl[1],bl[2],bl[3], bbl + off);
#pragma unroll
        for (int i = 0; i < MT; i++) {
            mma_bf16(acc[i][2*jp],   Ah[i], bh);
            mma_bf16(acc[i][2*jp],   Ah[i], bl);
            mma_bf16(acc[i][2*jp],   Al[i], bh);
            mma_bf16(acc[i][2*jp+1], Ah[i], bh+2);
            mma_bf16(acc[i][2*jp+1], Ah[i], bl+2);
            mma_bf16(acc[i][2*jp+1], Al[i], bh+2);
        }
    }
}

// ---------------- split conversion (merged, grid.y = tag) ----------------
__global__ __launch_bounds__(256) void convert_all(
    const float* __restrict__ x,  const float* __restrict__ Wq,
    const float* __restrict__ Wk, const float* __restrict__ Wv,
    const float* __restrict__ Wo)
{
    int tag = blockIdx.y;
    const float* src; bf16 *h, *l; int n4;
    if (tag == 0)      { src=x;  h = g_xh;  l = g_xl;  n4 = NB*SFULL*EMB/4; }
    else if (tag == 1) { src=Wq; h = g_Wqh; l = g_Wql; n4 = EMB*EMB/4; }
    else if (tag == 2) { src=Wk; h = g_Wkh; l = g_Wkl; n4 = EMB*EMB/4; }
    else if (tag == 3) { src=Wv; h = g_Wvh; l = g_Wvl; n4 = EMB*EMB/4; }
    else               { src=Wo; h = g_Woh; l = g_Wol; n4 = EMB*EMB/4; }
    int i = blockIdx.x * 256 + threadIdx.x;
    if (i >= n4) return;
    float4 v = ((const float4*)src)[i];
    bf16 h0,l0,h1,l1,h2,l2,h3,l3;
    split1(v.x,h0,l0); split1(v.y,h1,l1); split1(v.z,h2,l2); split1(v.w,h3,l3);
    bf162 hh0; hh0.x=h0; hh0.y=h1;  bf162 hh1; hh1.x=h2; hh1.y=h3;
    bf162 ll0; ll0.x=l0; ll0.y=l1;  bf162 ll1; ll1.x=l2; ll1.y=l3;
    ((bf162*)h)[2*i] = hh0; ((bf162*)h)[2*i+1] = hh1;
    ((bf162*)l)[2*i] = ll0; ((bf162*)l)[2*i+1] = ll1;
}

// ---------------- QKV projection (tensor, double-buffered) ----------------
__global__ __launch_bounds__(256) void qkv_tc(
    const float* __restrict__ bq, const float* __restrict__ bk, const float* __restrict__ bv)
{
    const bf16 *Wh, *Wl; const float* bias; bf16 *Ch, *Cl;
    int z = blockIdx.z;
    if (z == 0)      { Wh=g_Wqh; Wl=g_Wql; bias=bq; Ch=g_Qh; Cl=g_Ql; }
    else if (z == 1) { Wh=g_Wkh; Wl=g_Wkl; bias=bk; Ch=g_Kh; Cl=g_Kl; }
    else             { Wh=g_Wvh; Wl=g_Wvl; bias=bv; Ch=g_Vh; Cl=g_Vl; }

    __shared__ __align__(16) bf16 SAh[2][3072], SAl[2][3072], SBh[2][3072], SBl[2][3072];
    u32 pAh = sptr(SAh), pAl = sptr(SAl), pBh = sptr(SBh), pBl = sptr(SBl);
    int tid = threadIdx.x;
    int lane = tid & 31, wid = tid >> 5;
    int gid = lane >> 2, tig = lane & 3;
    int wm = wid >> 1, wn = wid & 1;
    int bm = blockIdx.y, bn = blockIdx.x;

    int arow = tid >> 1, ahalf = (tid & 1) << 3;
    int sidx = sx(arow, ahalf);
    int grow = bm*128 + arow;
    size_t aoff = (size_t)((grow>>10)*SFULL + 1 + (grow&1023)) * EMB + ahalf;
    size_t boff = (size_t)(bn*128 + arow) * EMB + ahalf;

    float acc[2][8][4];
#pragma unroll
    for (int i=0;i<2;i++)
#pragma unroll
        for (int j=0;j<8;j++)
#pragma unroll
            for (int q=0;q<4;q++) acc[i][j][q]=0.f;

    const int NK = EMB/16;
    *(uint4*)&SAh[0][sidx] = *(const uint4*)(g_xh + aoff);
    *(uint4*)&SAl[0][sidx] = *(const uint4*)(g_xl + aoff);
    *(uint4*)&SBh[0][sidx] = *(const uint4*)(Wh + boff);
    *(uint4*)&SBl[0][sidx] = *(const uint4*)(Wl + boff);
    uint4 rAh = *(const uint4*)(g_xh + aoff + 16);
    uint4 rAl = *(const uint4*)(g_xl + aoff + 16);
    uint4 rBh = *(const uint4*)(Wh + boff + 16);
    uint4 rBl = *(const uint4*)(Wl + boff + 16);
    __syncthreads();

    for (int ks = 0; ks < NK; ks++) {
        int cur = ks & 1;
        if (ks+1 < NK) {
            int nxt = cur ^ 1;
            *(uint4*)&SAh[nxt][sidx] = rAh;
            *(uint4*)&SAl[nxt][sidx] = rAl;
            *(uint4*)&SBh[nxt][sidx] = rBh;
            *(uint4*)&SBl[nxt][sidx] = rBl;
            if (ks+2 < NK) {
                size_t k2 = (size_t)(ks+2)*16;
                rAh = *(const uint4*)(g_xh + aoff + k2);
                rAl = *(const uint4*)(g_xl + aoff + k2);
                rBh = *(const uint4*)(Wh + boff + k2);
                rBl = *(const uint4*)(Wl + boff + k2);
            }
        }
        u32 Ahf[2][4], Alf[2][4];
        u32 ob = (u32)cur * 6144u;
        load_afrag<2>(Ahf, Alf, pAh + ob, pAl + ob, wm*32, lane);
        mma_block<2,8>(acc, Ahf, Alf, pBh + ob, pBl + ob, wn*64, lane);
        __syncthreads();
    }

#pragma unroll
    for (int i=0;i<2;i++) {
        int row0 = bm*128 + wm*32 + 16*i + gid;
#pragma unroll
        for (int j=0;j<8;j++) {
            int col0 = bn*128 + wn*64 + 8*j + 2*tig;
            float2 bv2 = *(const float2*)(bias + col0);
            float v0 = acc[i][j][0]+bv2.x, v1 = acc[i][j][1]+bv2.y;
            float v2 = acc[i][j][2]+bv2.x, v3 = acc[i][j][3]+bv2.y;
            size_t o0 = (size_t)row0*EMB + col0, o8 = (size_t)(row0+8)*EMB + col0;
            bf16 h,l; bf162 th, tl;
            split1(v0,h,l); th.x=h; tl.x=l; split1(v1,h,l); th.y=h; tl.y=l;
            *(bf162*)(Ch+o0)=th; *(bf162*)(Cl+o0)=tl;
            split1(v2,h,l); th.x=h; tl.x=l; split1(v3,h,l); th.y=h; tl.y=l;
            *(bf162*)(Ch+o8)=th; *(bf162*)(Cl+o8)=tl;
        }
    }
}

// ---------------- out projection (tensor, double-buffered) ----------------
__global__ __launch_bounds__(256) void out_tc(const float* __restrict__ bo, float* __restrict__ out)
{
    __shared__ __align__(16) bf16 SAh[2][3072], SAl[2][3072], SBh[2][3072], SBl[2][3072];
    u32 pAh = sptr(SAh), pAl = sptr(SAl), pBh = sptr(SBh), pBl = sptr(SBl);
    int tid = threadIdx.x;
    int lane = tid & 31, wid = tid >> 5;
    int gid = lane >> 2, tig = lane & 3;
    int wm = wid >> 1, wn = wid & 1;
    int bm = blockIdx.y, bn = blockIdx.x;

    int arow = tid >> 1, ahalf = (tid & 1) << 3;
    int sidx = sx(arow, ahalf);
    int grow = bm*128 + arow; if (grow >= MOUT) grow = MOUT-1;
    size_t aoff = (size_t)grow * EMB + ahalf;
    size_t boff = (size_t)(bn*128 + arow) * EMB + ahalf;

    float acc[2][8][4];
#pragma unroll
    for (int i=0;i<2;i++)
#pragma unroll
        for (int j=0;j<8;j++)
#pragma unroll
            for (int q=0;q<4;q++) acc[i][j][q]=0.f;

    const int NK = EMB/16;
    *(uint4*)&SAh[0][sidx] = *(const uint4*)(g_Yh + aoff);
    *(uint4*)&SAl[0][sidx] = *(const uint4*)(g_Yl + aoff);
    *(uint4*)&SBh[0][sidx] = *(const uint4*)(g_Woh + boff);
    *(uint4*)&SBl[0][sidx] = *(const uint4*)(g_Wol + boff);
    uint4 rAh = *(const uint4*)(g_Yh + aoff + 16);
    uint4 rAl = *(const uint4*)(g_Yl + aoff + 16);
    uint4 rBh = *(const uint4*)(g_Woh + boff + 16);
    uint4 rBl = *(const uint4*)(g_Wol + boff + 16);
    __syncthreads();

    for (int ks = 0; ks < NK; ks++) {
        int cur = ks & 1;
        if (ks+1 < NK) {
            int nxt = cur ^ 1;
            *(uint4*)&SAh[nxt][sidx] = rAh;
            *(uint4*)&SAl[nxt][sidx] = rAl;
            *(uint4*)&SBh[nxt][sidx] = rBh;
            *(uint4*)&SBl[nxt][sidx] = rBl;
            if (ks+2 < NK) {
                size_t k2 = (size_t)(ks+2)*16;
                rAh = *(const uint4*)(g_Yh + aoff + k2);
                rAl = *(const uint4*)(g_Yl + aoff + k2);
                rBh = *(const uint4*)(g_Woh + boff + k2);
                rBl = *(const uint4*)(g_Wol + boff + k2);
            }
        }
        u32 Ahf[2][4], Alf[2][4];
        u32 ob = (u32)cur * 6144u;
        load_afrag<2>(Ahf, Alf, pAh + ob, pAl + ob, wm*32, lane);
        mma_block<2,8>(acc, Ahf, Alf, pBh + ob, pBl + ob, wn*64, lane);
        __syncthreads();
    }

#pragma unroll
    for (int i=0;i<2;i++) {
        int row0 = bm*128 + wm*32 + 16*i + gid;
#pragma unroll
        for (int j=0;j<8;j++) {
            int col0 = bn*128 + wn*64 + 8*j + 2*tig;
            float2 bv2 = *(const float2*)(bo + col0);
            if (row0 < MOUT)
                *(float2*)(out + (size_t)row0*EMB + col0) =
                    make_float2(acc[i][j][0]+bv2.x, acc[i][j][1]+bv2.y);
            if (row0+8 < MOUT)
                *(float2*)(out + (size_t)(row0+8)*EMB + col0) =
                    make_float2(acc[i][j][2]+bv2.x, acc[i][j][3]+bv2.y);
        }
    }
}

// ---------------- score (full preload via cp.async, streaming stores) ------
__global__ __launch_bounds__(256) void score_tc(float* __restrict__ attn)
{
    extern __shared__ __align__(16) bf16 dsm[];
    bf16* SQh = dsm;
    bf16* SQl = dsm + 12288;
    bf16* SKh = dsm + 24576;
    bf16* SKl = dsm + 36864;
    u32 pQh = sptr(SQh), pQl = sptr(SQl), pKh = sptr(SKh), pKl = sptr(SKl);

    int bh = blockIdx.z;
    int b = bh / NH, h = bh % NH;
    int tid = threadIdx.x;
    int lane = tid & 31, wid = tid >> 5;
    int gid = lane >> 2, tig = lane & 3;
    int wm = wid >> 1, wn = wid & 1;
    int bm = blockIdx.y, bn = blockIdx.x;

#pragma unroll
    for (int part = 0; part < 4; part++) {
        int u = tid + 256*part;
        int row = u >> 3, g = u & 7;
        int kstep = g >> 1, c8 = (g & 1) << 3;
        u32 si = 2u * (kstep*3072 + sx(row, c8));
        size_t qo = (size_t)(b*SEQ + bm*128 + row)*EMB + h*HD + kstep*16 + c8;
        size_t ko = (size_t)(b*SEQ + bn*128 + row)*EMB + h*HD + kstep*16 + c8;
        cpa16(pQh + si, g_Qh + qo);
        cpa16(pQl + si, g_Ql + qo);
        cpa16(pKh + si, g_Kh + ko);
        cpa16(pKl + si, g_Kl + ko);
    }
    cpa_commit();
    cpa_wait<0>();
    __syncthreads();

    u32 AH[4][2][4], AL[4][2][4];
    {
        int r = wm*32 + (lane & 15);
        int kc = (lane >> 4) << 3;
#pragma unroll
        for (int ks = 0; ks < 4; ks++)
#pragma unroll
            for (int i = 0; i < 2; i++) {
                u32 off = 2u * (ks*3072 + sx(r + 16*i, kc));
                ldsm4(AH[ks][i][0],AH[ks][i][1],AH[ks][i][2],AH[ks][i][3], pQh + off);
                ldsm4(AL[ks][i][0],AL[ks][i][1],AL[ks][i][2],AL[ks][i][3], pQl + off);
            }
    }

    float acc[2][8][4];
#pragma unroll
    for (int i=0;i<2;i++)
#pragma unroll
        for (int j=0;j<8;j++)
#pragma unroll
            for (int q=0;q<4;q++) acc[i][j][q]=0.f;

    int nrow = (lane & 7) + ((lane >> 4) << 3);
    int kcb = ((lane >> 3) & 1) << 3;
#pragma unroll
    for (int ks = 0; ks < 4; ks++) {
        u32 kb = 2u*(ks*3072);
#pragma unroll
        for (int jp = 0; jp < 4; jp++) {
            u32 off = kb + 2u * sx(wn*64 + 16*jp + nrow, kcb);
            u32 bhf[4], blf[4];
            ldsm4(bhf[0],bhf[1],bhf[2],bhf[3], pKh + off);
            ldsm4(blf[0],blf[1],blf[2],blf[3], pKl + off);
#pragma unroll
            for (int i = 0; i < 2; i++) {
                mma_bf16(acc[i][2*jp],   AH[ks][i], bhf);
                mma_bf16(acc[i][2*jp],   AH[ks][i], blf);
                mma_bf16(acc[i][2*jp],   AL[ks][i], bhf);
                mma_bf16(acc[i][2*jp+1], AH[ks][i], bhf+2);
                mma_bf16(acc[i][2*jp+1], AH[ks][i], blf+2);
                mma_bf16(acc[i][2*jp+1], AL[ks][i], bhf+2);
            }
        }
    }

    float* Cb = attn + (size_t)bh*SEQ*SEQ;
    const float* coefp = g_coef + bh*SEQ;
#pragma unroll
    for (int i=0;i<2;i++) {
        int row0 = bm*128 + wm*32 + 16*i + gid;
        float cf0 = coefp[row0], cf8 = coefp[row0+8];
#pragma unroll
        for (int j=0;j<8;j++) {
            int col0 = bn*128 + wn*64 + 8*j + 2*tig;
            __stcs((float2*)(Cb + (size_t)row0*SEQ + col0),
                   make_float2(acc[i][j][0]*cf0, acc[i][j][1]*cf0));
            __stcs((float2*)(Cb + (size_t)(row0+8)*SEQ + col0),
                   make_float2(acc[i][j][2]*cf8, acc[i][j][3]*cf8));
        }
    }
}
#define SCORE_SMEM (4*12288*2)

// ---------------- attn @ V + fused softmax ----------------
// Pass 1: each thread streams its half-row, online (m,s); combine with lane^1.
// Mainloop: normalize at load (pass-2 reads are L2-resident), write final attn.
__global__ __launch_bounds__(256) void av_tc(float* __restrict__ attn)
{
    extern __shared__ __align__(16) bf16 dsm2[];
    bf16* SAh = dsm2;                 // 12288
    bf16* SAl = dsm2 + 12288;         // 12288
    bf16* SVh = dsm2 + 24576;         // 4608
    bf16* SVl = dsm2 + 29184;         // 4608
    u32 pAh = sptr(SAh), pAl = sptr(SAl), pVh = sptr(SVh), pVl = sptr(SVl);

    int bh = blockIdx.y;
    int b = bh / NH, h = bh % NH;
    int tid = threadIdx.x;
    int lane = tid & 31, wid = tid >> 5;
    int gid = lane >> 2, tig = lane & 3;
    int wm = wid >> 1, wn = wid & 1;
    int bm = blockIdx.x;

    int arow = tid >> 1, ahalf = (tid & 1) << 3;
    int sidx = sx(arow, ahalf);
    size_t aoff = (size_t)(bh*SEQ + bm*128 + arow)*SEQ + ahalf;

    // ---- pass 1: online softmax stats over this thread's half-row ----
    float m = -1e30f, s = 0.f;
    for (int c = 0; c < 64; c++) {
        float v[8];
        *(float4*)&v[0] = *(const float4*)(attn + aoff + c*16);
        *(float4*)&v[4] = *(const float4*)(attn + aoff + c*16 + 4);
        float cm = v[0];
#pragma unroll
        for (int e = 1; e < 8; e++) cm = fmaxf(cm, v[e]);
        float mn = fmaxf(m, cm);
        float cs = 0.f;
#pragma unroll
        for (int e = 0; e < 8; e++) cs += __expf(v[e] - mn);
        s = s * __expf(m - mn) + cs;
        m = mn;
    }
    {   // combine with partner lane (same row, other half)
        float m2 = __shfl_xor_sync(0xffffffffu, m, 1);
        float s2 = __shfl_xor_sync(0xffffffffu, s, 1);
        float M = fmaxf(m, m2);
        s = s * __expf(m - M) + s2 * __expf(m2 - M);
        m = M;
    }
    float rm = m, rinv = 1.0f / s;

    int tv = tid & 127;
    int vk = tv >> 3, vd0 = (tv & 7) << 3;
    const bf16* Vsrc = (tid < 128) ? g_Vh : g_Vl;
    int vsel = (tid < 128) ? 0 : 1;
    size_t voff = (size_t)(b*SEQ + vk)*EMB + h*HD + vd0;

    float acc[2][4][4];
#pragma unroll
    for (int i=0;i<2;i++)
#pragma unroll
        for (int j=0;j<4;j++)
#pragma unroll
            for (int q=0;q<4;q++) acc[i][j][q]=0.f;

    int bk = (lane & 7) + (((lane >> 3) & 1) << 3);
    int bdoff = (lane >> 4) << 3;

    const int NS = SEQ/32;
    // stage iteration 0 (ksteps 0,1): normalize at load, write final attn
#pragma unroll
    for (int j = 0; j < 2; j++) {
        float av[8];
        *(float4*)&av[0] = *(const float4*)(attn + aoff + j*16);
        *(float4*)&av[4] = *(const float4*)(attn + aoff + j*16 + 4);
#pragma unroll
        for (int e = 0; e < 8; e++) av[e] = __expf(av[e] - rm) * rinv;
        __stcs((float4*)(attn + aoff + j*16),     *(float4*)&av[0]);
        __stcs((float4*)(attn + aoff + j*16 + 4), *(float4*)&av[4]);
        uint4 H, L; split8(av, H, L);
        *(uint4*)&SAh[j*3072 + sidx] = H;
        *(uint4*)&SAl[j*3072 + sidx] = L;
        uint4 v0 = *(const uint4*)(Vsrc + voff + (size_t)j*16*EMB);
        if (vsel == 0) *(uint4*)&SVh[j*1152 + vk*72 + vd0] = v0;
        else           *(uint4*)&SVl[j*1152 + vk*72 + vd0] = v0;
    }
    float rA[16];
    uint4 rV[2];
#pragma unroll
    for (int j = 0; j < 2; j++) {
        *(float4*)&rA[j*8]   = *(const float4*)(attn + aoff + (2+j)*16);
        *(float4*)&rA[j*8+4] = *(const float4*)(attn + aoff + (2+j)*16 + 4);
#pragma unroll
        for (int e = 0; e < 8; e++) rA[j*8+e] = __expf(rA[j*8+e] - rm) * rinv;
        __stcs((float4*)(attn + aoff + (2+j)*16),     *(float4*)&rA[j*8]);
        __stcs((float4*)(attn + aoff + (2+j)*16 + 4), *(float4*)&rA[j*8+4]);
        rV[j] = *(const uint4*)(Vsrc + voff + (size_t)(2+j)*16*EMB);
    }
    __syncthreads();

    for (int it = 0; it < NS; it++) {
        int cur = it & 1;
        if (it+1 < NS) {
            int nxt = cur ^ 1;
#pragma unroll
            for (int j = 0; j < 2; j++) {
                uint4 H, L; split8(&rA[j*8], H, L);
                *(uint4*)&SAh[nxt*6144 + j*3072 + sidx] = H;
                *(uint4*)&SAl[nxt*6144 + j*3072 + sidx] = L;
                if (vsel == 0) *(uint4*)&SVh[nxt*2304 + j*1152 + vk*72 + vd0] = rV[j];
                else           *(uint4*)&SVl[nxt*2304 + j*1152 + vk*72 + vd0] = rV[j];
            }
            if (it+2 < NS) {
#pragma unroll
                for (int j = 0; j < 2; j++) {
                    int kst = (it+2)*2 + j;
                    *(float4*)&rA[j*8]   = *(const float4*)(attn + aoff + kst*16);
                    *(float4*)&rA[j*8+4] = *(const float4*)(attn + aoff + kst*16 + 4);
#pragma unroll
                    for (int e = 0; e < 8; e++) rA[j*8+e] = __expf(rA[j*8+e] - rm) * rinv;
                    __stcs((float4*)(attn + aoff + kst*16),     *(float4*)&rA[j*8]);
                    __stcs((float4*)(attn + aoff + kst*16 + 4), *(float4*)&rA[j*8+4]);
                    rV[j] = *(const uint4*)(Vsrc + voff + (size_t)kst*16*EMB);
                }
            }
        }
#pragma unroll
        for (int j = 0; j < 2; j++) {
            u32 obA = (u32)(cur*6144 + j*3072), obV = (u32)(cur*2304 + j*1152);
            u32 Ahf[2][4], Alf[2][4];
            load_afrag<2>(Ahf, Alf, pAh + 2u*obA, pAl + 2u*obA, wm*32, lane);
#pragma unroll
            for (int jp = 0; jp < 2; jp++) {
                int d = wn*32 + 16*jp + bdoff;
                u32 off = 2u * (obV + bk*72 + d);
                u32 bhf[4], blf[4];
                ldsm4t(bhf[0],bhf[1],bhf[2],bhf[3], pVh + off);
                ldsm4t(blf[0],blf[1],blf[2],blf[3], pVl + off);
#pragma unroll
                for (int i = 0; i < 2; i++) {
                    mma_bf16(acc[i][2*jp],   Ahf[i], bhf);
                    mma_bf16(acc[i][2*jp],   Ahf[i], blf);
                    mma_bf16(acc[i][2*jp],   Alf[i], bhf);
                    mma_bf16(acc[i][2*jp+1], Ahf[i], bhf+2);
                    mma_bf16(acc[i][2*jp+1], Ahf[i], blf+2);
                    mma_bf16(acc[i][2*jp+1], Alf[i], bhf+2);
                }
            }
        }
        __syncthreads();
    }

#pragma unroll
    for (int i=0;i<2;i++) {
        int row0 = bm*128 + wm*32 + 16*i + gid;
#pragma unroll
        for (int j=0;j<4;j++) {
            int col0 = wn*32 + 8*j + 2*tig;
            size_t o0 = (size_t)(b*SFULL + 1 + row0)*EMB + h*HD + col0;
            size_t o8 = (size_t)(b*SFULL + 9 + row0)*EMB + h*HD + col0;
            bf16 hh,ll; bf162 th, tl;
            split1(acc[i][j][0],hh,ll); th.x=hh; tl.x=ll;
            split1(acc[i][j][1],hh,ll); th.y=hh; tl.y=ll;
            *(bf162*)(g_Yh+o0)=th; *(bf162*)(g_Yl+o0)=tl;
            split1(acc[i][j][2],hh,ll); th.x=hh; tl.x=ll;
            split1(acc[i][j][3],hh,ll); th.y=hh; tl.y=ll;
            *(bf162*)(g_Yh+o8)=th; *(bf162*)(g_Yl+o8)=tl;
        }
    }
}
#define AV_SMEM ((12288*2 + 4608*2) * 2)

// ---------------- c projection ----------------
__global__ void cproj_kernel(const float* __restrict__ x,
                             const float* __restrict__ Wc,
                             const float* __restrict__ bc)
{
    int b = blockIdx.x;
    __shared__ float xs[EMB];
    for (int e = threadIdx.x; e < EMB; e += blockDim.x)
        xs[e] = x[(size_t)b * SFULL * EMB + e];
    __syncthreads();
    for (int j = threadIdx.x; j < EMB; j += blockDim.x) {
        const float* w = Wc + (size_t)j * EMB;
        float acc = bc[j];
        for (int e = 0; e < EMB; e++) acc += xs[e] * w[e];
        g_C[b * EMB + j] = acc;
    }
}

// ---------------- coefficients (from bf16 h+l) ----------------
__global__ __launch_bounds__(256) void coef_kernel()
{
    int gw = blockIdx.x * 8 + (threadIdx.x >> 5);
    int lane = threadIdx.x & 31;
    int q = gw & (SEQ - 1);
    int bh = gw >> 10;
    int b = bh / NH, h = bh % NH;
    const bf16* srcH = (blockIdx.y == 0) ? g_Qh : g_Kh;
    const bf16* srcL = (blockIdx.y == 0) ? g_Ql : g_Kl;
    size_t qo = (size_t)(b * SEQ + q) * EMB + h * HD;
    const float* cp = g_C + b * EMB + h * HD;
    float q0 = __bfloat162float(srcH[qo+lane]) + __bfloat162float(srcL[qo+lane]);
    float q1 = __bfloat162float(srcH[qo+lane+32]) + __bfloat162float(srcL[qo+lane+32]);
    float c0 = cp[lane], c1 = cp[lane + 32];
    float qn = q0*q0 + q1*q1;
    float cq = c0*q0 + c1*q1;
    float cn = c0*c0 + c1*c1;
#pragma unroll
    for (int o = 16; o; o >>= 1) {
        qn += __shfl_xor_sync(0xffffffffu, qn, o);
        cq += __shfl_xor_sync(0xffffffffu, cq, o);
        cn += __shfl_xor_sync(0xffffffffu, cn, o);
    }
    if (lane == 0) {
        float cn2 = fmaxf(cn, 1e-5f);
        if (blockIdx.y == 0) {
            float qn2 = fmaxf(qn, 1e-5f);
            g_coef[gw] = cq / (qn2 * sqrtf(64.0f * cn2));
        } else {
            g_ck[gw] = cq / sqrtf(64.0f * cn2);
        }
    }
}

// ---------------- CLS row (V from bf16 h+l) ----------------
__global__ void cls_kernel(const float* __restrict__ x)
{
    int bh = blockIdx.x;
    int b = bh / NH, h = bh % NH;
    int d = threadIdx.x;  // 64 threads
    __shared__ float cks[SEQ];
    for (int k = d; k < SEQ; k += 64) cks[k] = g_ck[bh * SEQ + k];
    __syncthreads();
    size_t vb = (size_t)b * SEQ * EMB + h * HD + d;
    float acc = 0.f;
#pragma unroll 8
    for (int k = 0; k < SEQ; k++) {
        float v = __bfloat162float(g_Vh[vb + (size_t)k * EMB])
                + __bfloat162float(g_Vl[vb + (size_t)k * EMB]);
        acc += cks[k] * v;
    }
    float cls = x[(size_t)b * SFULL * EMB + h * HD + d];
    float y = 0.5f * (cls + acc);
    size_t o = (size_t)b * SFULL * EMB + h * HD + d;
    bf16 hh, ll; split1(y, hh, ll);
    g_Yh[o] = hh; g_Yl[o] = ll;
}

// ---------------------------------------------------------------------------
extern "C" void kernel_launch(void* const* d_in, const int* in_sizes, int n_in,
                              void* d_out, int out_size)
{
    const float* x  = (const float*)d_in[0];
    const float* Wq = (const float*)d_in[1]; const float* bq = (const float*)d_in[2];
    const float* Wk = (const float*)d_in[3]; const float* bk = (const float*)d_in[4];
    const float* Wv = (const float*)d_in[5]; const float* bv = (const float*)d_in[6];
    const float* Wc = (const float*)d_in[7]; const float* bc = (const float*)d_in[8];
    const float* Wo = (const float*)d_in[9]; const float* bo = (const float*)d_in[10];

    float* out  = (float*)d_out;
    float* attn = out + (size_t)NB * SFULL * EMB;

    cudaFuncSetAttribute(score_tc, cudaFuncAttributeMaxDynamicSharedMemorySize, SCORE_SMEM);
    cudaFuncSetAttribute(av_tc, cudaFuncAttributeMaxDynamicSharedMemorySize, AV_SMEM);

    int nx4 = NB*SFULL*EMB/4;
    convert_all<<<dim3((nx4+255)/256, 5), 256>>>(x, Wq, Wk, Wv, Wo); // 1
    cproj_kernel<<<8, 256>>>(x, Wc, bc);                             // 2
    qkv_tc<<<dim3(6, 64, 3), 256>>>(bq, bk, bv);                     // 3
    coef_kernel<<<dim3(12288, 2), 256>>>();                          // 4
    score_tc<<<dim3(8, 8, 96), 256, SCORE_SMEM>>>(attn);             // 5
    av_tc<<<dim3(8, 96), 256, AV_SMEM>>>(attn);                      // 6
    cls_kernel<<<96, 64>>>(x);                                       // 7
    out_tc<<<dim3(6, 65), 256>>>(bo, out);                           // 8
}

// round 16
// speedup vs baseline: 1.0995x; 1.0995x over previous
#include <cuda_runtime.h>
#include <cuda_bf16.h>

#define NB 8
#define SEQ 1024
#define SFULL 1025
#define EMB 768
#define NH 12
#define HD 64
#define BH (NB*NH)   // 96
#define MOUT (NB*SFULL) // 8200

typedef unsigned u32;
typedef __nv_bfloat16 bf16;
typedef __nv_bfloat162 bf162;

// ---------------- static scratch ----------------
__device__ float g_C[NB*EMB];
__device__ float g_coef[BH*SEQ];
__device__ float g_ck[BH*SEQ];

__device__ bf16 g_xh[NB*SFULL*EMB], g_xl[NB*SFULL*EMB];
__device__ bf16 g_Wqh[EMB*EMB], g_Wql[EMB*EMB];
__device__ bf16 g_Wkh[EMB*EMB], g_Wkl[EMB*EMB];
__device__ bf16 g_Wvh[EMB*EMB], g_Wvl[EMB*EMB];
__device__ bf16 g_Woh[EMB*EMB], g_Wol[EMB*EMB];
__device__ bf16 g_Qh[NB*SEQ*EMB], g_Ql[NB*SEQ*EMB];
__device__ bf16 g_Kh[NB*SEQ*EMB], g_Kl[NB*SEQ*EMB];
__device__ bf16 g_Vh[NB*SEQ*EMB], g_Vl[NB*SEQ*EMB];
__device__ bf16 g_Yh[NB*SFULL*EMB], g_Yl[NB*SFULL*EMB];

// ---------------- helpers ----------------
__device__ __forceinline__ void mma_bf16(float* d, const u32* a, const u32* b) {
    asm("mma.sync.aligned.m16n8k16.row.col.f32.bf16.bf16.f32 "
        "{%0,%1,%2,%3},{%4,%5,%6,%7},{%8,%9},{%0,%1,%2,%3};"
        : "+f"(d[0]), "+f"(d[1]), "+f"(d[2]), "+f"(d[3])
        : "r"(a[0]), "r"(a[1]), "r"(a[2]), "r"(a[3]), "r"(b[0]), "r"(b[1]));
}
__device__ __forceinline__ void ldsm4(u32& r0,u32& r1,u32& r2,u32& r3, u32 addr){
    asm volatile("ldmatrix.sync.aligned.m8n8.x4.shared.b16 {%0,%1,%2,%3},[%4];"
        : "=r"(r0),"=r"(r1),"=r"(r2),"=r"(r3) : "r"(addr));
}
__device__ __forceinline__ void ldsm4t(u32& r0,u32& r1,u32& r2,u32& r3, u32 addr){
    asm volatile("ldmatrix.sync.aligned.m8n8.x4.trans.shared.b16 {%0,%1,%2,%3},[%4];"
        : "=r"(r0),"=r"(r1),"=r"(r2),"=r"(r3) : "r"(addr));
}
__device__ __forceinline__ u32 sptr(const void* p){
    return (u32)__cvta_generic_to_shared(p);
}
__device__ __forceinline__ void cpa16(u32 saddr, const void* g){
    asm volatile("cp.async.cg.shared.global [%0],[%1],16;" :: "r"(saddr), "l"(g));
}
__device__ __forceinline__ void cpa_commit(){
    asm volatile("cp.async.commit_group;");
}
template<int N>
__device__ __forceinline__ void cpa_wait(){
    asm volatile("cp.async.wait_group %0;" :: "n"(N));
}
// swizzled smem index (stride 24 bf16/row, XOR 8-col halves by row bit3)
__device__ __forceinline__ int sx(int r, int c) { return r*24 + (c ^ (((r>>3)&1)<<3)); }

__device__ __forceinline__ void split1(float v, bf16& h, bf16& l) {
    h = __float2bfloat16(v);
    l = __float2bfloat16(v - __bfloat162float(h));
}
__device__ __forceinline__ void split8(const float* v, uint4& H, uint4& L) {
    bf16 hh[8], ll[8];
#pragma unroll
    for (int e = 0; e < 8; e++) split1(v[e], hh[e], ll[e]);
    H = *(uint4*)hh; L = *(uint4*)ll;
}

template<int MT>
__device__ __forceinline__ void load_afrag(u32 Ah[][4], u32 Al[][4],
                                           u32 baseh, u32 basel, int rbase, int lane)
{
    int r = rbase + (lane & 15);
    int kc = (lane >> 4) << 3;
#pragma unroll
    for (int i = 0; i < MT; i++) {
        u32 off = 2u * sx(r + 16*i, kc);
        ldsm4(Ah[i][0],Ah[i][1],Ah[i][2],Ah[i][3], baseh + off);
        ldsm4(Al[i][0],Al[i][1],Al[i][2],Al[i][3], basel + off);
    }
}

template<int MT, int NT>
__device__ __forceinline__ void mma_block(
    float acc[MT][NT][4], const u32 Ah[][4], const u32 Al[][4],
    u32 bbh, u32 bbl, int cbase, int lane)
{
    int nrow = (lane & 7) + ((lane >> 4) << 3);
    int kc = ((lane >> 3) & 1) << 3;
#pragma unroll
    for (int jp = 0; jp < NT/2; jp++) {
        u32 off = 2u * sx(cbase + 16*jp + nrow, kc);
        u32 bh[4], bl[4];
        ldsm4(bh[0],bh[1],bh[2],bh[3], bbh + off);
        ldsm4(bl[0],bl[1],bl[2],bl[3], bbl + off);
#pragma unroll
        for (int i = 0; i < MT; i++) {
            mma_bf16(acc[i][2*jp],   Ah[i], bh);
            mma_bf16(acc[i][2*jp],   Ah[i], bl);
            mma_bf16(acc[i][2*jp],   Al[i], bh);
            mma_bf16(acc[i][2*jp+1], Ah[i], bh+2);
            mma_bf16(acc[i][2*jp+1], Ah[i], bl+2);
            mma_bf16(acc[i][2*jp+1], Al[i], bh+2);
        }
    }
}

// ---------------- split conversion (merged, grid.y = tag) ----------------
__global__ __launch_bounds__(256) void convert_all(
    const float* __restrict__ x,  const float* __restrict__ Wq,
    const float* __restrict__ Wk, const float* __restrict__ Wv,
    const float* __restrict__ Wo)
{
    int tag = blockIdx.y;
    const float* src; bf16 *h, *l; int n4;
    if (tag == 0)      { src=x;  h = g_xh;  l = g_xl;  n4 = NB*SFULL*EMB/4; }
    else if (tag == 1) { src=Wq; h = g_Wqh; l = g_Wql; n4 = EMB*EMB/4; }
    else if (tag == 2) { src=Wk; h = g_Wkh; l = g_Wkl; n4 = EMB*EMB/4; }
    else if (tag == 3) { src=Wv; h = g_Wvh; l = g_Wvl; n4 = EMB*EMB/4; }
    else               { src=Wo; h = g_Woh; l = g_Wol; n4 = EMB*EMB/4; }
    int i = blockIdx.x * 256 + threadIdx.x;
    if (i >= n4) return;
    float4 v = ((const float4*)src)[i];
    bf16 h0,l0,h1,l1,h2,l2,h3,l3;
    split1(v.x,h0,l0); split1(v.y,h1,l1); split1(v.z,h2,l2); split1(v.w,h3,l3);
    bf162 hh0; hh0.x=h0; hh0.y=h1;  bf162 hh1; hh1.x=h2; hh1.y=h3;
    bf162 ll0; ll0.x=l0; ll0.y=l1;  bf162 ll1; ll1.x=l2; ll1.y=l3;
    ((bf162*)h)[2*i] = hh0; ((bf162*)h)[2*i+1] = hh1;
    ((bf162*)l)[2*i] = ll0; ((bf162*)l)[2*i+1] = ll1;
}

// ---------------- QKV projection (tensor, double-buffered) ----------------
__global__ __launch_bounds__(256) void qkv_tc(
    const float* __restrict__ bq, const float* __restrict__ bk, const float* __restrict__ bv)
{
    const bf16 *Wh, *Wl; const float* bias; bf16 *Ch, *Cl;
    int z = blockIdx.z;
    if (z == 0)      { Wh=g_Wqh; Wl=g_Wql; bias=bq; Ch=g_Qh; Cl=g_Ql; }
    else if (z == 1) { Wh=g_Wkh; Wl=g_Wkl; bias=bk; Ch=g_Kh; Cl=g_Kl; }
    else             { Wh=g_Wvh; Wl=g_Wvl; bias=bv; Ch=g_Vh; Cl=g_Vl; }

    __shared__ __align__(16) bf16 SAh[2][3072], SAl[2][3072], SBh[2][3072], SBl[2][3072];
    u32 pAh = sptr(SAh), pAl = sptr(SAl), pBh = sptr(SBh), pBl = sptr(SBl);
    int tid = threadIdx.x;
    int lane = tid & 31, wid = tid >> 5;
    int gid = lane >> 2, tig = lane & 3;
    int wm = wid >> 1, wn = wid & 1;
    int bm = blockIdx.y, bn = blockIdx.x;

    int arow = tid >> 1, ahalf = (tid & 1) << 3;
    int sidx = sx(arow, ahalf);
    int grow = bm*128 + arow;
    size_t aoff = (size_t)((grow>>10)*SFULL + 1 + (grow&1023)) * EMB + ahalf;
    size_t boff = (size_t)(bn*128 + arow) * EMB + ahalf;

    float acc[2][8][4];
#pragma unroll
    for (int i=0;i<2;i++)
#pragma unroll
        for (int j=0;j<8;j++)
#pragma unroll
            for (int q=0;q<4;q++) acc[i][j][q]=0.f;

    const int NK = EMB/16;
    *(uint4*)&SAh[0][sidx] = *(const uint4*)(g_xh + aoff);
    *(uint4*)&SAl[0][sidx] = *(const uint4*)(g_xl + aoff);
    *(uint4*)&SBh[0][sidx] = *(const uint4*)(Wh + boff);
    *(uint4*)&SBl[0][sidx] = *(const uint4*)(Wl + boff);
    uint4 rAh = *(const uint4*)(g_xh + aoff + 16);
    uint4 rAl = *(const uint4*)(g_xl + aoff + 16);
    uint4 rBh = *(const uint4*)(Wh + boff + 16);
    uint4 rBl = *(const uint4*)(Wl + boff + 16);
    __syncthreads();

    for (int ks = 0; ks < NK; ks++) {
        int cur = ks & 1;
        if (ks+1 < NK) {
            int nxt = cur ^ 1;
            *(uint4*)&SAh[nxt][sidx] = rAh;
            *(uint4*)&SAl[nxt][sidx] = rAl;
            *(uint4*)&SBh[nxt][sidx] = rBh;
            *(uint4*)&SBl[nxt][sidx] = rBl;
            if (ks+2 < NK) {
                size_t k2 = (size_t)(ks+2)*16;
                rAh = *(const uint4*)(g_xh + aoff + k2);
                rAl = *(const uint4*)(g_xl + aoff + k2);
                rBh = *(const uint4*)(Wh + boff + k2);
                rBl = *(const uint4*)(Wl + boff + k2);
            }
        }
        u32 Ahf[2][4], Alf[2][4];
        u32 ob = (u32)cur * 6144u;
        load_afrag<2>(Ahf, Alf, pAh + ob, pAl + ob, wm*32, lane);
        mma_block<2,8>(acc, Ahf, Alf, pBh + ob, pBl + ob, wn*64, lane);
        __syncthreads();
    }

#pragma unroll
    for (int i=0;i<2;i++) {
        int row0 = bm*128 + wm*32 + 16*i + gid;
#pragma unroll
        for (int j=0;j<8;j++) {
            int col0 = bn*128 + wn*64 + 8*j + 2*tig;
            float2 bv2 = *(const float2*)(bias + col0);
            float v0 = acc[i][j][0]+bv2.x, v1 = acc[i][j][1]+bv2.y;
            float v2 = acc[i][j][2]+bv2.x, v3 = acc[i][j][3]+bv2.y;
            size_t o0 = (size_t)row0*EMB + col0, o8 = (size_t)(row0+8)*EMB + col0;
            bf16 h,l; bf162 th, tl;
            split1(v0,h,l); th.x=h; tl.x=l; split1(v1,h,l); th.y=h; tl.y=l;
            *(bf162*)(Ch+o0)=th; *(bf162*)(Cl+o0)=tl;
            split1(v2,h,l); th.x=h; tl.x=l; split1(v3,h,l); th.y=h; tl.y=l;
            *(bf162*)(Ch+o8)=th; *(bf162*)(Cl+o8)=tl;
        }
    }
}

// ---------------- out projection (tensor, double-buffered) ----------------
__global__ __launch_bounds__(256) void out_tc(const float* __restrict__ bo, float* __restrict__ out)
{
    __shared__ __align__(16) bf16 SAh[2][3072], SAl[2][3072], SBh[2][3072], SBl[2][3072];
    u32 pAh = sptr(SAh), pAl = sptr(SAl), pBh = sptr(SBh), pBl = sptr(SBl);
    int tid = threadIdx.x;
    int lane = tid & 31, wid = tid >> 5;
    int gid = lane >> 2, tig = lane & 3;
    int wm = wid >> 1, wn = wid & 1;
    int bm = blockIdx.y, bn = blockIdx.x;

    int arow = tid >> 1, ahalf = (tid & 1) << 3;
    int sidx = sx(arow, ahalf);
    int grow = bm*128 + arow; if (grow >= MOUT) grow = MOUT-1;
    size_t aoff = (size_t)grow * EMB + ahalf;
    size_t boff = (size_t)(bn*128 + arow) * EMB + ahalf;

    float acc[2][8][4];
#pragma unroll
    for (int i=0;i<2;i++)
#pragma unroll
        for (int j=0;j<8;j++)
#pragma unroll
            for (int q=0;q<4;q++) acc[i][j][q]=0.f;

    const int NK = EMB/16;
    *(uint4*)&SAh[0][sidx] = *(const uint4*)(g_Yh + aoff);
    *(uint4*)&SAl[0][sidx] = *(const uint4*)(g_Yl + aoff);
    *(uint4*)&SBh[0][sidx] = *(const uint4*)(g_Woh + boff);
    *(uint4*)&SBl[0][sidx] = *(const uint4*)(g_Wol + boff);
    uint4 rAh = *(const uint4*)(g_Yh + aoff + 16);
    uint4 rAl = *(const uint4*)(g_Yl + aoff + 16);
    uint4 rBh = *(const uint4*)(g_Woh + boff + 16);
    uint4 rBl = *(const uint4*)(g_Wol + boff + 16);
    __syncthreads();

    for (int ks = 0; ks < NK; ks++) {
        int cur = ks & 1;
        if (ks+1 < NK) {
            int nxt = cur ^ 1;
            *(uint4*)&SAh[nxt][sidx] = rAh;
            *(uint4*)&SAl[nxt][sidx] = rAl;
            *(uint4*)&SBh[nxt][sidx] = rBh;
            *(uint4*)&SBl[nxt][sidx] = rBl;
            if (ks+2 < NK) {
                size_t k2 = (size_t)(ks+2)*16;
                rAh = *(const uint4*)(g_Yh + aoff + k2);
                rAl = *(const uint4*)(g_Yl + aoff + k2);
                rBh = *(const uint4*)(g_Woh + boff + k2);
                rBl = *(const uint4*)(g_Wol + boff + k2);
            }
        }
        u32 Ahf[2][4], Alf[2][4];
        u32 ob = (u32)cur * 6144u;
        load_afrag<2>(Ahf, Alf, pAh + ob, pAl + ob, wm*32, lane);
        mma_block<2,8>(acc, Ahf, Alf, pBh + ob, pBl + ob, wn*64, lane);
        __syncthreads();
    }

#pragma unroll
    for (int i=0;i<2;i++) {
        int row0 = bm*128 + wm*32 + 16*i + gid;
#pragma unroll
        for (int j=0;j<8;j++) {
            int col0 = bn*128 + wn*64 + 8*j + 2*tig;
            float2 bv2 = *(const float2*)(bo + col0);
            if (row0 < MOUT)
                *(float2*)(out + (size_t)row0*EMB + col0) =
                    make_float2(acc[i][j][0]+bv2.x, acc[i][j][1]+bv2.y);
            if (row0+8 < MOUT)
                *(float2*)(out + (size_t)(row0+8)*EMB + col0) =
                    make_float2(acc[i][j][2]+bv2.x, acc[i][j][3]+bv2.y);
        }
    }
}

// ---------------- score (full preload via cp.async, streaming stores) ------
__global__ __launch_bounds__(256) void score_tc(float* __restrict__ attn)
{
    extern __shared__ __align__(16) bf16 dsm[];
    bf16* SQh = dsm;
    bf16* SQl = dsm + 12288;
    bf16* SKh = dsm + 24576;
    bf16* SKl = dsm + 36864;
    u32 pQh = sptr(SQh), pQl = sptr(SQl), pKh = sptr(SKh), pKl = sptr(SKl);

    int bh = blockIdx.z;
    int b = bh / NH, h = bh % NH;
    int tid = threadIdx.x;
    int lane = tid & 31, wid = tid >> 5;
    int gid = lane >> 2, tig = lane & 3;
    int wm = wid >> 1, wn = wid & 1;
    int bm = blockIdx.y, bn = blockIdx.x;

#pragma unroll
    for (int part = 0; part < 4; part++) {
        int u = tid + 256*part;
        int row = u >> 3, g = u & 7;
        int kstep = g >> 1, c8 = (g & 1) << 3;
        u32 si = 2u * (kstep*3072 + sx(row, c8));
        size_t qo = (size_t)(b*SEQ + bm*128 + row)*EMB + h*HD + kstep*16 + c8;
        size_t ko = (size_t)(b*SEQ + bn*128 + row)*EMB + h*HD + kstep*16 + c8;
        cpa16(pQh + si, g_Qh + qo);
        cpa16(pQl + si, g_Ql + qo);
        cpa16(pKh + si, g_Kh + ko);
        cpa16(pKl + si, g_Kl + ko);
    }
    cpa_commit();
    cpa_wait<0>();
    __syncthreads();

    u32 AH[4][2][4], AL[4][2][4];
    {
        int r = wm*32 + (lane & 15);
        int kc = (lane >> 4) << 3;
#pragma unroll
        for (int ks = 0; ks < 4; ks++)
#pragma unroll
            for (int i = 0; i < 2; i++) {
                u32 off = 2u * (ks*3072 + sx(r + 16*i, kc));
                ldsm4(AH[ks][i][0],AH[ks][i][1],AH[ks][i][2],AH[ks][i][3], pQh + off);
                ldsm4(AL[ks][i][0],AL[ks][i][1],AL[ks][i][2],AL[ks][i][3], pQl + off);
            }
    }

    float acc[2][8][4];
#pragma unroll
    for (int i=0;i<2;i++)
#pragma unroll
        for (int j=0;j<8;j++)
#pragma unroll
            for (int q=0;q<4;q++) acc[i][j][q]=0.f;

    int nrow = (lane & 7) + ((lane >> 4) << 3);
    int kcb = ((lane >> 3) & 1) << 3;
#pragma unroll
    for (int ks = 0; ks < 4; ks++) {
        u32 kb = 2u*(ks*3072);
#pragma unroll
        for (int jp = 0; jp < 4; jp++) {
            u32 off = kb + 2u * sx(wn*64 + 16*jp + nrow, kcb);
            u32 bhf[4], blf[4];
            ldsm4(bhf[0],bhf[1],bhf[2],bhf[3], pKh + off);
            ldsm4(blf[0],blf[1],blf[2],blf[3], pKl + off);
#pragma unroll
            for (int i = 0; i < 2; i++) {
                mma_bf16(acc[i][2*jp],   AH[ks][i], bhf);
                mma_bf16(acc[i][2*jp],   AH[ks][i], blf);
                mma_bf16(acc[i][2*jp],   AL[ks][i], bhf);
                mma_bf16(acc[i][2*jp+1], AH[ks][i], bhf+2);
                mma_bf16(acc[i][2*jp+1], AH[ks][i], blf+2);
                mma_bf16(acc[i][2*jp+1], AL[ks][i], bhf+2);
            }
        }
    }

    float* Cb = attn + (size_t)bh*SEQ*SEQ;
    const float* coefp = g_coef + bh*SEQ;
#pragma unroll
    for (int i=0;i<2;i++) {
        int row0 = bm*128 + wm*32 + 16*i + gid;
        float cf0 = coefp[row0], cf8 = coefp[row0+8];
#pragma unroll
        for (int j=0;j<8;j++) {
            int col0 = bn*128 + wn*64 + 8*j + 2*tig;
            __stcs((float2*)(Cb + (size_t)row0*SEQ + col0),
                   make_float2(acc[i][j][0]*cf0, acc[i][j][1]*cf0));
            __stcs((float2*)(Cb + (size_t)(row0+8)*SEQ + col0),
                   make_float2(acc[i][j][2]*cf8, acc[i][j][3]*cf8));
        }
    }
}
#define SCORE_SMEM (4*12288*2)

// ---------------- softmax (fp32 in-place, streaming) ----------------
__global__ __launch_bounds__(256) void softmax_kernel(float* __restrict__ attn)
{
    size_t row = blockIdx.x;
    float4* p = (float4*)(attn + row * SEQ);
    int t = threadIdx.x;
    int wid = t >> 5, lane = t & 31;
    __shared__ float redm[8], reds[8];

    float4 v = __ldcs(p + t);
    float m = fmaxf(fmaxf(v.x, v.y), fmaxf(v.z, v.w));
#pragma unroll
    for (int o = 16; o; o >>= 1) m = fmaxf(m, __shfl_xor_sync(0xffffffffu, m, o));
    if (lane == 0) redm[wid] = m;
    __syncthreads();
    m = redm[0];
#pragma unroll
    for (int i = 1; i < 8; i++) m = fmaxf(m, redm[i]);

    v.x = __expf(v.x - m); v.y = __expf(v.y - m);
    v.z = __expf(v.z - m); v.w = __expf(v.w - m);
    float s = v.x + v.y + v.z + v.w;
#pragma unroll
    for (int o = 16; o; o >>= 1) s += __shfl_xor_sync(0xffffffffu, s, o);
    if (lane == 0) reds[wid] = s;
    __syncthreads();
    s = reds[0];
#pragma unroll
    for (int i = 1; i < 8; i++) s += reds[i];

    float inv = 1.0f / s;
    v.x *= inv; v.y *= inv; v.z *= inv; v.w *= inv;
    __stcs(p + t, v);
}

// ---------------- attn @ V (tensor, fp32 A streaming reads) ---------------
__global__ __launch_bounds__(256) void av_tc(const float* __restrict__ attn)
{
    extern __shared__ __align__(16) bf16 dsm2[];
    bf16* SAh = dsm2;                 // 12288
    bf16* SAl = dsm2 + 12288;         // 12288
    bf16* SVh = dsm2 + 24576;         // 4608
    bf16* SVl = dsm2 + 29184;         // 4608
    u32 pAh = sptr(SAh), pAl = sptr(SAl), pVh = sptr(SVh), pVl = sptr(SVl);

    int bh = blockIdx.y;
    int b = bh / NH, h = bh % NH;
    int tid = threadIdx.x;
    int lane = tid & 31, wid = tid >> 5;
    int gid = lane >> 2, tig = lane & 3;
    int wm = wid >> 1, wn = wid & 1;
    int bm = blockIdx.x;

    int arow = tid >> 1, ahalf = (tid & 1) << 3;
    int sidx = sx(arow, ahalf);
    size_t aoff = (size_t)(bh*SEQ + bm*128 + arow)*SEQ + ahalf;

    int tv = tid & 127;
    int vk = tv >> 3, vd0 = (tv & 7) << 3;
    const bf16* Vsrc = (tid < 128) ? g_Vh : g_Vl;
    int vsel = (tid < 128) ? 0 : 1;
    size_t voff = (size_t)(b*SEQ + vk)*EMB + h*HD + vd0;

    float acc[2][4][4];
#pragma unroll
    for (int i=0;i<2;i++)
#pragma unroll
        for (int j=0;j<4;j++)
#pragma unroll
            for (int q=0;q<4;q++) acc[i][j][q]=0.f;

    int bk = (lane & 7) + (((lane >> 3) & 1) << 3);
    int bdoff = (lane >> 4) << 3;

    const int NS = SEQ/32;
#pragma unroll
    for (int j = 0; j < 2; j++) {
        float av[8];
        *(float4*)&av[0] = __ldcs((const float4*)(attn + aoff + j*16));
        *(float4*)&av[4] = __ldcs((const float4*)(attn + aoff + j*16 + 4));
        uint4 H, L; split8(av, H, L);
        *(uint4*)&SAh[j*3072 + sidx] = H;
        *(uint4*)&SAl[j*3072 + sidx] = L;
        uint4 v0 = *(const uint4*)(Vsrc + voff + (size_t)j*16*EMB);
        if (vsel == 0) *(uint4*)&SVh[j*1152 + vk*72 + vd0] = v0;
        else           *(uint4*)&SVl[j*1152 + vk*72 + vd0] = v0;
    }
    float rA[16];
    uint4 rV[2];
#pragma unroll
    for (int j = 0; j < 2; j++) {
        *(float4*)&rA[j*8]   = __ldcs((const float4*)(attn + aoff + (2+j)*16));
        *(float4*)&rA[j*8+4] = __ldcs((const float4*)(attn + aoff + (2+j)*16 + 4));
        rV[j] = *(const uint4*)(Vsrc + voff + (size_t)(2+j)*16*EMB);
    }
    __syncthreads();

    for (int it = 0; it < NS; it++) {
        int cur = it & 1;
        if (it+1 < NS) {
            int nxt = cur ^ 1;
#pragma unroll
            for (int j = 0; j < 2; j++) {
                uint4 H, L; split8(&rA[j*8], H, L);
                *(uint4*)&SAh[nxt*6144 + j*3072 + sidx] = H;
                *(uint4*)&SAl[nxt*6144 + j*3072 + sidx] = L;
                if (vsel == 0) *(uint4*)&SVh[nxt*2304 + j*1152 + vk*72 + vd0] = rV[j];
                else           *(uint4*)&SVl[nxt*2304 + j*1152 + vk*72 + vd0] = rV[j];
            }
            if (it+2 < NS) {
#pragma unroll
                for (int j = 0; j < 2; j++) {
                    int kst = (it+2)*2 + j;
                    *(float4*)&rA[j*8]   = __ldcs((const float4*)(attn + aoff + kst*16));
                    *(float4*)&rA[j*8+4] = __ldcs((const float4*)(attn + aoff + kst*16 + 4));
                    rV[j] = *(const uint4*)(Vsrc + voff + (size_t)kst*16*EMB);
                }
            }
        }
#pragma unroll
        for (int j = 0; j < 2; j++) {
            u32 obA = (u32)(cur*6144 + j*3072), obV = (u32)(cur*2304 + j*1152);
            u32 Ahf[2][4], Alf[2][4];
            load_afrag<2>(Ahf, Alf, pAh + 2u*obA, pAl + 2u*obA, wm*32, lane);
#pragma unroll
            for (int jp = 0; jp < 2; jp++) {
                int d = wn*32 + 16*jp + bdoff;
                u32 off = 2u * (obV + bk*72 + d);
                u32 bhf[4], blf[4];
                ldsm4t(bhf[0],bhf[1],bhf[2],bhf[3], pVh + off);
                ldsm4t(blf[0],blf[1],blf[2],blf[3], pVl + off);
#pragma unroll
                for (int i = 0; i < 2; i++) {
                    mma_bf16(acc[i][2*jp],   Ahf[i], bhf);
                    mma_bf16(acc[i][2*jp],   Ahf[i], blf);
                    mma_bf16(acc[i][2*jp],   Alf[i], bhf);
                    mma_bf16(acc[i][2*jp+1], Ahf[i], bhf+2);
                    mma_bf16(acc[i][2*jp+1], Ahf[i], blf+2);
                    mma_bf16(acc[i][2*jp+1], Alf[i], bhf+2);
                }
            }
        }
        __syncthreads();
    }

#pragma unroll
    for (int i=0;i<2;i++) {
        int row0 = bm*128 + wm*32 + 16*i + gid;
#pragma unroll
        for (int j=0;j<4;j++) {
            int col0 = wn*32 + 8*j + 2*tig;
            size_t o0 = (size_t)(b*SFULL + 1 + row0)*EMB + h*HD + col0;
            size_t o8 = (size_t)(b*SFULL + 9 + row0)*EMB + h*HD + col0;
            bf16 hh,ll; bf162 th, tl;
            split1(acc[i][j][0],hh,ll); th.x=hh; tl.x=ll;
            split1(acc[i][j][1],hh,ll); th.y=hh; tl.y=ll;
            *(bf162*)(g_Yh+o0)=th; *(bf162*)(g_Yl+o0)=tl;
            split1(acc[i][j][2],hh,ll); th.x=hh; tl.x=ll;
            split1(acc[i][j][3],hh,ll); th.y=hh; tl.y=ll;
            *(bf162*)(g_Yh+o8)=th; *(bf162*)(g_Yl+o8)=tl;
        }
    }
}
#define AV_SMEM ((12288*2 + 4608*2) * 2)

// ---------------- c projection ----------------
__global__ void cproj_kernel(const float* __restrict__ x,
                             const float* __restrict__ Wc,
                             const float* __restrict__ bc)
{
    int b = blockIdx.x;
    __shared__ float xs[EMB];
    for (int e = threadIdx.x; e < EMB; e += blockDim.x)
        xs[e] = x[(size_t)b * SFULL * EMB + e];
    __syncthreads();
    for (int j = threadIdx.x; j < EMB; j += blockDim.x) {
        const float* w = Wc + (size_t)j * EMB;
        float acc = bc[j];
        for (int e = 0; e < EMB; e++) acc += xs[e] * w[e];
        g_C[b * EMB + j] = acc;
    }
}

// ---------------- coefficients (from bf16 h+l) ----------------
__global__ __launch_bounds__(256) void coef_kernel()
{
    int gw = blockIdx.x * 8 + (threadIdx.x >> 5);
    int lane = threadIdx.x & 31;
    int q = gw & (SEQ - 1);
    int bh = gw >> 10;
    int b = bh / NH, h = bh % NH;
    const bf16* srcH = (blockIdx.y == 0) ? g_Qh : g_Kh;
    const bf16* srcL = (blockIdx.y == 0) ? g_Ql : g_Kl;
    size_t qo = (size_t)(b * SEQ + q) * EMB + h * HD;
    const float* cp = g_C + b * EMB + h * HD;
    float q0 = __bfloat162float(srcH[qo+lane]) + __bfloat162float(srcL[qo+lane]);
    float q1 = __bfloat162float(srcH[qo+lane+32]) + __bfloat162float(srcL[qo+lane+32]);
    float c0 = cp[lane], c1 = cp[lane + 32];
    float qn = q0*q0 + q1*q1;
    float cq = c0*q0 + c1*q1;
    float cn = c0*c0 + c1*c1;
#pragma unroll
    for (int o = 16; o; o >>= 1) {
        qn += __shfl_xor_sync(0xffffffffu, qn, o);
        cq += __shfl_xor_sync(0xffffffffu, cq, o);
        cn += __shfl_xor_sync(0xffffffffu, cn, o);
    }
    if (lane == 0) {
        float cn2 = fmaxf(cn, 1e-5f);
        if (blockIdx.y == 0) {
            float qn2 = fmaxf(qn, 1e-5f);
            g_coef[gw] = cq / (qn2 * sqrtf(64.0f * cn2));
        } else {
            g_ck[gw] = cq / sqrtf(64.0f * cn2);
        }
    }
}

// ---------------- CLS row (V from bf16 h+l) ----------------
__global__ void cls_kernel(const float* __restrict__ x)
{
    int bh = blockIdx.x;
    int b = bh / NH, h = bh % NH;
    int d = threadIdx.x;  // 64 threads
    __shared__ float cks[SEQ];
    for (int k = d; k < SEQ; k += 64) cks[k] = g_ck[bh * SEQ + k];
    __syncthreads();
    size_t vb = (size_t)b * SEQ * EMB + h * HD + d;
    float acc = 0.f;
#pragma unroll 8
    for (int k = 0; k < SEQ; k++) {
        float v = __bfloat162float(g_Vh[vb + (size_t)k * EMB])
                + __bfloat162float(g_Vl[vb + (size_t)k * EMB]);
        acc += cks[k] * v;
    }
    float cls = x[(size_t)b * SFULL * EMB + h * HD + d];
    float y = 0.5f * (cls + acc);
    size_t o = (size_t)b * SFULL * EMB + h * HD + d;
    bf16 hh, ll; split1(y, hh, ll);
    g_Yh[o] = hh; g_Yl[o] = ll;
}

// ---------------------------------------------------------------------------
extern "C" void kernel_launch(void* const* d_in, const int* in_sizes, int n_in,
                              void* d_out, int out_size)
{
    const float* x  = (const float*)d_in[0];
    const float* Wq = (const float*)d_in[1]; const float* bq = (const float*)d_in[2];
    const float* Wk = (const float*)d_in[3]; const float* bk = (const float*)d_in[4];
    const float* Wv = (const float*)d_in[5]; const float* bv = (const float*)d_in[6];
    const float* Wc = (const float*)d_in[7]; const float* bc = (const float*)d_in[8];
    const float* Wo = (const float*)d_in[9]; const float* bo = (const float*)d_in[10];

    float* out  = (float*)d_out;
    float* attn = out + (size_t)NB * SFULL * EMB;

    cudaFuncSetAttribute(score_tc, cudaFuncAttributeMaxDynamicSharedMemorySize, SCORE_SMEM);
    cudaFuncSetAttribute(av_tc, cudaFuncAttributeMaxDynamicSharedMemorySize, AV_SMEM);

    int nx4 = NB*SFULL*EMB/4;
    convert_all<<<dim3((nx4+255)/256, 5), 256>>>(x, Wq, Wk, Wv, Wo); // 1
    cproj_kernel<<<8, 256>>>(x, Wc, bc);                             // 2
    qkv_tc<<<dim3(6, 64, 3), 256>>>(bq, bk, bv);                     // 3
    coef_kernel<<<dim3(12288, 2), 256>>>();                          // 4
    score_tc<<<dim3(8, 8, 96), 256, SCORE_SMEM>>>(attn);             // 5
    softmax_kernel<<<BH * SEQ, 256>>>(attn);                         // 6
    av_tc<<<dim3(8, 96), 256, AV_SMEM>>>(attn);                      // 7
    cls_kernel<<<96, 64>>>(x);                                       // 8
    out_tc<<<dim3(6, 65), 256>>>(bo, out);                           // 9
}

// round 17
// speedup vs baseline: 1.1332x; 1.0307x over previous
#include <cuda_runtime.h>
#include <cuda_bf16.h>

#define NB 8
#define SEQ 1024
#define SFULL 1025
#define EMB 768
#define NH 12
#define HD 64
#define BH (NB*NH)   // 96
#define MOUT (NB*SFULL) // 8200

typedef unsigned u32;
typedef __nv_bfloat16 bf16;
typedef __nv_bfloat162 bf162;

// ---------------- static scratch ----------------
__device__ float g_C[NB*EMB];
__device__ float g_coef[BH*SEQ];
__device__ float g_ck[BH*SEQ];
__device__ int   g_scnt[BH*8];     // score row-group completion counters

__device__ bf16 g_xh[NB*SFULL*EMB], g_xl[NB*SFULL*EMB];
__device__ bf16 g_Wqh[EMB*EMB], g_Wql[EMB*EMB];
__device__ bf16 g_Wkh[EMB*EMB], g_Wkl[EMB*EMB];
__device__ bf16 g_Wvh[EMB*EMB], g_Wvl[EMB*EMB];
__device__ bf16 g_Woh[EMB*EMB], g_Wol[EMB*EMB];
__device__ bf16 g_Qh[NB*SEQ*EMB], g_Ql[NB*SEQ*EMB];
__device__ bf16 g_Kh[NB*SEQ*EMB], g_Kl[NB*SEQ*EMB];
__device__ bf16 g_Vh[NB*SEQ*EMB], g_Vl[NB*SEQ*EMB];
__device__ bf16 g_Yh[NB*SFULL*EMB], g_Yl[NB*SFULL*EMB];

// ---------------- helpers ----------------
__device__ __forceinline__ void mma_bf16(float* d, const u32* a, const u32* b) {
    asm("mma.sync.aligned.m16n8k16.row.col.f32.bf16.bf16.f32 "
        "{%0,%1,%2,%3},{%4,%5,%6,%7},{%8,%9},{%0,%1,%2,%3};"
        : "+f"(d[0]), "+f"(d[1]), "+f"(d[2]), "+f"(d[3])
        : "r"(a[0]), "r"(a[1]), "r"(a[2]), "r"(a[3]), "r"(b[0]), "r"(b[1]));
}
__device__ __forceinline__ void ldsm4(u32& r0,u32& r1,u32& r2,u32& r3, u32 addr){
    asm volatile("ldmatrix.sync.aligned.m8n8.x4.shared.b16 {%0,%1,%2,%3},[%4];"
        : "=r"(r0),"=r"(r1),"=r"(r2),"=r"(r3) : "r"(addr));
}
__device__ __forceinline__ void ldsm4t(u32& r0,u32& r1,u32& r2,u32& r3, u32 addr){
    asm volatile("ldmatrix.sync.aligned.m8n8.x4.trans.shared.b16 {%0,%1,%2,%3},[%4];"
        : "=r"(r0),"=r"(r1),"=r"(r2),"=r"(r3) : "r"(addr));
}
__device__ __forceinline__ u32 sptr(const void* p){
    return (u32)__cvta_generic_to_shared(p);
}
__device__ __forceinline__ void cpa16(u32 saddr, const void* g){
    asm volatile("cp.async.cg.shared.global [%0],[%1],16;" :: "r"(saddr), "l"(g));
}
__device__ __forceinline__ void cpa_commit(){
    asm volatile("cp.async.commit_group;");
}
template<int N>
__device__ __forceinline__ void cpa_wait(){
    asm volatile("cp.async.wait_group %0;" :: "n"(N));
}
// swizzled smem index (stride 24 bf16/row, XOR 8-col halves by row bit3)
__device__ __forceinline__ int sx(int r, int c) { return r*24 + (c ^ (((r>>3)&1)<<3)); }

__device__ __forceinline__ void split1(float v, bf16& h, bf16& l) {
    h = __float2bfloat16(v);
    l = __float2bfloat16(v - __bfloat162float(h));
}
__device__ __forceinline__ void split8(const float* v, uint4& H, uint4& L) {
    bf16 hh[8], ll[8];
#pragma unroll
    for (int e = 0; e < 8; e++) split1(v[e], hh[e], ll[e]);
    H = *(uint4*)hh; L = *(uint4*)ll;
}

template<int MT>
__device__ __forceinline__ void load_afrag(u32 Ah[][4], u32 Al[][4],
                                           u32 baseh, u32 basel, int rbase, int lane)
{
    int r = rbase + (lane & 15);
    int kc = (lane >> 4) << 3;
#pragma unroll
    for (int i = 0; i < MT; i++) {
        u32 off = 2u * sx(r + 16*i, kc);
        ldsm4(Ah[i][0],Ah[i][1],Ah[i][2],Ah[i][3], baseh + off);
        ldsm4(Al[i][0],Al[i][1],Al[i][2],Al[i][3], basel + off);
    }
}

template<int MT, int NT>
__device__ __forceinline__ void mma_block(
    float acc[MT][NT][4], const u32 Ah[][4], const u32 Al[][4],
    u32 bbh, u32 bbl, int cbase, int lane)
{
    int nrow = (lane & 7) + ((lane >> 4) << 3);
    int kc = ((lane >> 3) & 1) << 3;
#pragma unroll
    for (int jp = 0; jp < NT/2; jp++) {
        u32 off = 2u * sx(cbase + 16*jp + nrow, kc);
        u32 bh[4], bl[4];
        ldsm4(bh[0],bh[1],bh[2],bh[3], bbh + off);
        ldsm4(bl[0],bl[1],bl[2],bl[3], bbl + off);
#pragma unroll
        for (int i = 0; i < MT; i++) {
            mma_bf16(acc[i][2*jp],   Ah[i], bh);
            mma_bf16(acc[i][2*jp],   Ah[i], bl);
            mma_bf16(acc[i][2*jp],   Al[i], bh);
            mma_bf16(acc[i][2*jp+1], Ah[i], bh+2);
            mma_bf16(acc[i][2*jp+1], Ah[i], bl+2);
            mma_bf16(acc[i][2*jp+1], Al[i], bh+2);
        }
    }
}

// ---------------- split conversion (merged, grid.y = tag) ----------------
__global__ __launch_bounds__(256) void convert_all(
    const float* __restrict__ x,  const float* __restrict__ Wq,
    const float* __restrict__ Wk, const float* __restrict__ Wv,
    const float* __restrict__ Wo)
{
    int tag = blockIdx.y;
    const float* src; bf16 *h, *l; int n4;
    if (tag == 0)      { src=x;  h = g_xh;  l = g_xl;  n4 = NB*SFULL*EMB/4; }
    else if (tag == 1) { src=Wq; h = g_Wqh; l = g_Wql; n4 = EMB*EMB/4; }
    else if (tag == 2) { src=Wk; h = g_Wkh; l = g_Wkl; n4 = EMB*EMB/4; }
    else if (tag == 3) { src=Wv; h = g_Wvh; l = g_Wvl; n4 = EMB*EMB/4; }
    else               { src=Wo; h = g_Woh; l = g_Wol; n4 = EMB*EMB/4; }
    int i = blockIdx.x * 256 + threadIdx.x;
    if (i >= n4) return;
    float4 v = ((const float4*)src)[i];
    bf16 h0,l0,h1,l1,h2,l2,h3,l3;
    split1(v.x,h0,l0); split1(v.y,h1,l1); split1(v.z,h2,l2); split1(v.w,h3,l3);
    bf162 hh0; hh0.x=h0; hh0.y=h1;  bf162 hh1; hh1.x=h2; hh1.y=h3;
    bf162 ll0; ll0.x=l0; ll0.y=l1;  bf162 ll1; ll1.x=l2; ll1.y=l3;
    ((bf162*)h)[2*i] = hh0; ((bf162*)h)[2*i+1] = hh1;
    ((bf162*)l)[2*i] = ll0; ((bf162*)l)[2*i+1] = ll1;
}

// ---------------- QKV projection (tensor, double-buffered) ----------------
__global__ __launch_bounds__(256) void qkv_tc(
    const float* __restrict__ bq, const float* __restrict__ bk, const float* __restrict__ bv)
{
    const bf16 *Wh, *Wl; const float* bias; bf16 *Ch, *Cl;
    int z = blockIdx.z;
    if (z == 0)      { Wh=g_Wqh; Wl=g_Wql; bias=bq; Ch=g_Qh; Cl=g_Ql; }
    else if (z == 1) { Wh=g_Wkh; Wl=g_Wkl; bias=bk; Ch=g_Kh; Cl=g_Kl; }
    else             { Wh=g_Wvh; Wl=g_Wvl; bias=bv; Ch=g_Vh; Cl=g_Vl; }

    __shared__ __align__(16) bf16 SAh[2][3072], SAl[2][3072], SBh[2][3072], SBl[2][3072];
    u32 pAh = sptr(SAh), pAl = sptr(SAl), pBh = sptr(SBh), pBl = sptr(SBl);
    int tid = threadIdx.x;
    int lane = tid & 31, wid = tid >> 5;
    int gid = lane >> 2, tig = lane & 3;
    int wm = wid >> 1, wn = wid & 1;
    int bm = blockIdx.y, bn = blockIdx.x;

    int arow = tid >> 1, ahalf = (tid & 1) << 3;
    int sidx = sx(arow, ahalf);
    int grow = bm*128 + arow;
    size_t aoff = (size_t)((grow>>10)*SFULL + 1 + (grow&1023)) * EMB + ahalf;
    size_t boff = (size_t)(bn*128 + arow) * EMB + ahalf;

    float acc[2][8][4];
#pragma unroll
    for (int i=0;i<2;i++)
#pragma unroll
        for (int j=0;j<8;j++)
#pragma unroll
            for (int q=0;q<4;q++) acc[i][j][q]=0.f;

    const int NK = EMB/16;
    *(uint4*)&SAh[0][sidx] = *(const uint4*)(g_xh + aoff);
    *(uint4*)&SAl[0][sidx] = *(const uint4*)(g_xl + aoff);
    *(uint4*)&SBh[0][sidx] = *(const uint4*)(Wh + boff);
    *(uint4*)&SBl[0][sidx] = *(const uint4*)(Wl + boff);
    uint4 rAh = *(const uint4*)(g_xh + aoff + 16);
    uint4 rAl = *(const uint4*)(g_xl + aoff + 16);
    uint4 rBh = *(const uint4*)(Wh + boff + 16);
    uint4 rBl = *(const uint4*)(Wl + boff + 16);
    __syncthreads();

    for (int ks = 0; ks < NK; ks++) {
        int cur = ks & 1;
        if (ks+1 < NK) {
            int nxt = cur ^ 1;
            *(uint4*)&SAh[nxt][sidx] = rAh;
            *(uint4*)&SAl[nxt][sidx] = rAl;
            *(uint4*)&SBh[nxt][sidx] = rBh;
            *(uint4*)&SBl[nxt][sidx] = rBl;
            if (ks+2 < NK) {
                size_t k2 = (size_t)(ks+2)*16;
                rAh = *(const uint4*)(g_xh + aoff + k2);
                rAl = *(const uint4*)(g_xl + aoff + k2);
                rBh = *(const uint4*)(Wh + boff + k2);
                rBl = *(const uint4*)(Wl + boff + k2);
            }
        }
        u32 Ahf[2][4], Alf[2][4];
        u32 ob = (u32)cur * 6144u;
        load_afrag<2>(Ahf, Alf, pAh + ob, pAl + ob, wm*32, lane);
        mma_block<2,8>(acc, Ahf, Alf, pBh + ob, pBl + ob, wn*64, lane);
        __syncthreads();
    }

#pragma unroll
    for (int i=0;i<2;i++) {
        int row0 = bm*128 + wm*32 + 16*i + gid;
#pragma unroll
        for (int j=0;j<8;j++) {
            int col0 = bn*128 + wn*64 + 8*j + 2*tig;
            float2 bv2 = *(const float2*)(bias + col0);
            float v0 = acc[i][j][0]+bv2.x, v1 = acc[i][j][1]+bv2.y;
            float v2 = acc[i][j][2]+bv2.x, v3 = acc[i][j][3]+bv2.y;
            size_t o0 = (size_t)row0*EMB + col0, o8 = (size_t)(row0+8)*EMB + col0;
            bf16 h,l; bf162 th, tl;
            split1(v0,h,l); th.x=h; tl.x=l; split1(v1,h,l); th.y=h; tl.y=l;
            *(bf162*)(Ch+o0)=th; *(bf162*)(Cl+o0)=tl;
            split1(v2,h,l); th.x=h; tl.x=l; split1(v3,h,l); th.y=h; tl.y=l;
            *(bf162*)(Ch+o8)=th; *(bf162*)(Cl+o8)=tl;
        }
    }
}

// ---------------- out projection (tensor, double-buffered) ----------------
__global__ __launch_bounds__(256) void out_tc(const float* __restrict__ bo, float* __restrict__ out)
{
    __shared__ __align__(16) bf16 SAh[2][3072], SAl[2][3072], SBh[2][3072], SBl[2][3072];
    u32 pAh = sptr(SAh), pAl = sptr(SAl), pBh = sptr(SBh), pBl = sptr(SBl);
    int tid = threadIdx.x;
    int lane = tid & 31, wid = tid >> 5;
    int gid = lane >> 2, tig = lane & 3;
    int wm = wid >> 1, wn = wid & 1;
    int bm = blockIdx.y, bn = blockIdx.x;

    int arow = tid >> 1, ahalf = (tid & 1) << 3;
    int sidx = sx(arow, ahalf);
    int grow = bm*128 + arow; if (grow >= MOUT) grow = MOUT-1;
    size_t aoff = (size_t)grow * EMB + ahalf;
    size_t boff = (size_t)(bn*128 + arow) * EMB + ahalf;

    float acc[2][8][4];
#pragma unroll
    for (int i=0;i<2;i++)
#pragma unroll
        for (int j=0;j<8;j++)
#pragma unroll
            for (int q=0;q<4;q++) acc[i][j][q]=0.f;

    const int NK = EMB/16;
    *(uint4*)&SAh[0][sidx] = *(const uint4*)(g_Yh + aoff);
    *(uint4*)&SAl[0][sidx] = *(const uint4*)(g_Yl + aoff);
    *(uint4*)&SBh[0][sidx] = *(const uint4*)(g_Woh + boff);
    *(uint4*)&SBl[0][sidx] = *(const uint4*)(g_Wol + boff);
    uint4 rAh = *(const uint4*)(g_Yh + aoff + 16);
    uint4 rAl = *(const uint4*)(g_Yl + aoff + 16);
    uint4 rBh = *(const uint4*)(g_Woh + boff + 16);
    uint4 rBl = *(const uint4*)(g_Wol + boff + 16);
    __syncthreads();

    for (int ks = 0; ks < NK; ks++) {
        int cur = ks & 1;
        if (ks+1 < NK) {
            int nxt = cur ^ 1;
            *(uint4*)&SAh[nxt][sidx] = rAh;
            *(uint4*)&SAl[nxt][sidx] = rAl;
            *(uint4*)&SBh[nxt][sidx] = rBh;
            *(uint4*)&SBl[nxt][sidx] = rBl;
            if (ks+2 < NK) {
                size_t k2 = (size_t)(ks+2)*16;
                rAh = *(const uint4*)(g_Yh + aoff + k2);
                rAl = *(const uint4*)(g_Yl + aoff + k2);
                rBh = *(const uint4*)(g_Woh + boff + k2);
                rBl = *(const uint4*)(g_Wol + boff + k2);
            }
        }
        u32 Ahf[2][4], Alf[2][4];
        u32 ob = (u32)cur * 6144u;
        load_afrag<2>(Ahf, Alf, pAh + ob, pAl + ob, wm*32, lane);
        mma_block<2,8>(acc, Ahf, Alf, pBh + ob, pBl + ob, wn*64, lane);
        __syncthreads();
    }

#pragma unroll
    for (int i=0;i<2;i++) {
        int row0 = bm*128 + wm*32 + 16*i + gid;
#pragma unroll
        for (int j=0;j<8;j++) {
            int col0 = bn*128 + wn*64 + 8*j + 2*tig;
            float2 bv2 = *(const float2*)(bo + col0);
            if (row0 < MOUT)
                *(float2*)(out + (size_t)row0*EMB + col0) =
                    make_float2(acc[i][j][0]+bv2.x, acc[i][j][1]+bv2.y);
            if (row0+8 < MOUT)
                *(float2*)(out + (size_t)(row0+8)*EMB + col0) =
                    make_float2(acc[i][j][2]+bv2.x, acc[i][j][3]+bv2.y);
        }
    }
}

// ---------------- score + last-CTA softmax ----------------
// Raw logits stored with normal caching (short L2 window); the 8th CTA of each
// (bm,bh) row-group normalizes its 128 rows warp-per-row; normalized attn
// written with streaming hint (long window until av).
__global__ __launch_bounds__(256) void score_tc(float* __restrict__ attn)
{
    extern __shared__ __align__(16) bf16 dsm[];
    bf16* SQh = dsm;
    bf16* SQl = dsm + 12288;
    bf16* SKh = dsm + 24576;
    bf16* SKl = dsm + 36864;
    u32 pQh = sptr(SQh), pQl = sptr(SQl), pKh = sptr(SKh), pKl = sptr(SKl);

    int bh = blockIdx.z;
    int b = bh / NH, h = bh % NH;
    int tid = threadIdx.x;
    int lane = tid & 31, wid = tid >> 5;
    int gid = lane >> 2, tig = lane & 3;
    int wm = wid >> 1, wn = wid & 1;
    int bm = blockIdx.y, bn = blockIdx.x;

#pragma unroll
    for (int part = 0; part < 4; part++) {
        int u = tid + 256*part;
        int row = u >> 3, g = u & 7;
        int kstep = g >> 1, c8 = (g & 1) << 3;
        u32 si = 2u * (kstep*3072 + sx(row, c8));
        size_t qo = (size_t)(b*SEQ + bm*128 + row)*EMB + h*HD + kstep*16 + c8;
        size_t ko = (size_t)(b*SEQ + bn*128 + row)*EMB + h*HD + kstep*16 + c8;
        cpa16(pQh + si, g_Qh + qo);
        cpa16(pQl + si, g_Ql + qo);
        cpa16(pKh + si, g_Kh + ko);
        cpa16(pKl + si, g_Kl + ko);
    }
    cpa_commit();
    cpa_wait<0>();
    __syncthreads();

    u32 AH[4][2][4], AL[4][2][4];
    {
        int r = wm*32 + (lane & 15);
        int kc = (lane >> 4) << 3;
#pragma unroll
        for (int ks = 0; ks < 4; ks++)
#pragma unroll
            for (int i = 0; i < 2; i++) {
                u32 off = 2u * (ks*3072 + sx(r + 16*i, kc));
                ldsm4(AH[ks][i][0],AH[ks][i][1],AH[ks][i][2],AH[ks][i][3], pQh + off);
                ldsm4(AL[ks][i][0],AL[ks][i][1],AL[ks][i][2],AL[ks][i][3], pQl + off);
            }
    }

    float acc[2][8][4];
#pragma unroll
    for (int i=0;i<2;i++)
#pragma unroll
        for (int j=0;j<8;j++)
#pragma unroll
            for (int q=0;q<4;q++) acc[i][j][q]=0.f;

    int nrow = (lane & 7) + ((lane >> 4) << 3);
    int kcb = ((lane >> 3) & 1) << 3;
#pragma unroll
    for (int ks = 0; ks < 4; ks++) {
        u32 kb = 2u*(ks*3072);
#pragma unroll
        for (int jp = 0; jp < 4; jp++) {
            u32 off = kb + 2u * sx(wn*64 + 16*jp + nrow, kcb);
            u32 bhf[4], blf[4];
            ldsm4(bhf[0],bhf[1],bhf[2],bhf[3], pKh + off);
            ldsm4(blf[0],blf[1],blf[2],blf[3], pKl + off);
#pragma unroll
            for (int i = 0; i < 2; i++) {
                mma_bf16(acc[i][2*jp],   AH[ks][i], bhf);
                mma_bf16(acc[i][2*jp],   AH[ks][i], blf);
                mma_bf16(acc[i][2*jp],   AL[ks][i], bhf);
                mma_bf16(acc[i][2*jp+1], AH[ks][i], bhf+2);
                mma_bf16(acc[i][2*jp+1], AH[ks][i], blf+2);
                mma_bf16(acc[i][2*jp+1], AL[ks][i], bhf+2);
            }
        }
    }

    float* Cb = attn + (size_t)bh*SEQ*SEQ;
    const float* coefp = g_coef + bh*SEQ;
#pragma unroll
    for (int i=0;i<2;i++) {
        int row0 = bm*128 + wm*32 + 16*i + gid;
        float cf0 = coefp[row0], cf8 = coefp[row0+8];
#pragma unroll
        for (int j=0;j<8;j++) {
            int col0 = bn*128 + wn*64 + 8*j + 2*tig;
            *(float2*)(Cb + (size_t)row0*SEQ + col0) =
                make_float2(acc[i][j][0]*cf0, acc[i][j][1]*cf0);
            *(float2*)(Cb + (size_t)(row0+8)*SEQ + col0) =
                make_float2(acc[i][j][2]*cf8, acc[i][j][3]*cf8);
        }
    }

    // ---- last-CTA softmax for this (bm, bh) row-group ----
    __threadfence();
    __syncthreads();
    __shared__ int s_old;
    if (tid == 0) s_old = atomicAdd(&g_scnt[bh*8 + bm], 1);
    __syncthreads();
    if (s_old == 7) {
        __threadfence();   // acquire: order reads after observing all arrivals
        float* Rb = Cb + (size_t)bm*128*SEQ;
        for (int r = wid; r < 128; r += 8) {
            float* row = Rb + (size_t)r*SEQ;
            float4 v[8];
#pragma unroll
            for (int c = 0; c < 8; c++)
                v[c] = *(const float4*)(row + lane*4 + c*128);
            float m = -1e30f;
#pragma unroll
            for (int c = 0; c < 8; c++)
                m = fmaxf(m, fmaxf(fmaxf(v[c].x,v[c].y), fmaxf(v[c].z,v[c].w)));
#pragma unroll
            for (int o = 16; o; o >>= 1) m = fmaxf(m, __shfl_xor_sync(0xffffffffu, m, o));
            float s = 0.f;
#pragma unroll
            for (int c = 0; c < 8; c++) {
                v[c].x = __expf(v[c].x - m); v[c].y = __expf(v[c].y - m);
                v[c].z = __expf(v[c].z - m); v[c].w = __expf(v[c].w - m);
                s += v[c].x + v[c].y + v[c].z + v[c].w;
            }
#pragma unroll
            for (int o = 16; o; o >>= 1) s += __shfl_xor_sync(0xffffffffu, s, o);
            float inv = 1.0f / s;
#pragma unroll
            for (int c = 0; c < 8; c++) {
                float4 w4 = v[c];
                w4.x *= inv; w4.y *= inv; w4.z *= inv; w4.w *= inv;
                __stcs((float4*)(row + lane*4 + c*128), w4);
            }
        }
    }
}
#define SCORE_SMEM (4*12288*2)

// ---------------- attn @ V (tensor, fp32 A streaming reads) ---------------
__global__ __launch_bounds__(256) void av_tc(const float* __restrict__ attn)
{
    extern __shared__ __align__(16) bf16 dsm2[];
    bf16* SAh = dsm2;                 // 12288
    bf16* SAl = dsm2 + 12288;         // 12288
    bf16* SVh = dsm2 + 24576;         // 4608
    bf16* SVl = dsm2 + 29184;         // 4608
    u32 pAh = sptr(SAh), pAl = sptr(SAl), pVh = sptr(SVh), pVl = sptr(SVl);

    int bh = blockIdx.y;
    int b = bh / NH, h = bh % NH;
    int tid = threadIdx.x;
    int lane = tid & 31, wid = tid >> 5;
    int gid = lane >> 2, tig = lane & 3;
    int wm = wid >> 1, wn = wid & 1;
    int bm = blockIdx.x;

    int arow = tid >> 1, ahalf = (tid & 1) << 3;
    int sidx = sx(arow, ahalf);
    size_t aoff = (size_t)(bh*SEQ + bm*128 + arow)*SEQ + ahalf;

    int tv = tid & 127;
    int vk = tv >> 3, vd0 = (tv & 7) << 3;
    const bf16* Vsrc = (tid < 128) ? g_Vh : g_Vl;
    int vsel = (tid < 128) ? 0 : 1;
    size_t voff = (size_t)(b*SEQ + vk)*EMB + h*HD + vd0;

    float acc[2][4][4];
#pragma unroll
    for (int i=0;i<2;i++)
#pragma unroll
        for (int j=0;j<4;j++)
#pragma unroll
            for (int q=0;q<4;q++) acc[i][j][q]=0.f;

    int bk = (lane & 7) + (((lane >> 3) & 1) << 3);
    int bdoff = (lane >> 4) << 3;

    const int NS = SEQ/32;
#pragma unroll
    for (int j = 0; j < 2; j++) {
        float av[8];
        *(float4*)&av[0] = __ldcs((const float4*)(attn + aoff + j*16));
        *(float4*)&av[4] = __ldcs((const float4*)(attn + aoff + j*16 + 4));
        uint4 H, L; split8(av, H, L);
        *(uint4*)&SAh[j*3072 + sidx] = H;
        *(uint4*)&SAl[j*3072 + sidx] = L;
        uint4 v0 = *(const uint4*)(Vsrc + voff + (size_t)j*16*EMB);
        if (vsel == 0) *(uint4*)&SVh[j*1152 + vk*72 + vd0] = v0;
        else           *(uint4*)&SVl[j*1152 + vk*72 + vd0] = v0;
    }
    float rA[16];
    uint4 rV[2];
#pragma unroll
    for (int j = 0; j < 2; j++) {
        *(float4*)&rA[j*8]   = __ldcs((const float4*)(attn + aoff + (2+j)*16));
        *(float4*)&rA[j*8+4] = __ldcs((const float4*)(attn + aoff + (2+j)*16 + 4));
        rV[j] = *(const uint4*)(Vsrc + voff + (size_t)(2+j)*16*EMB);
    }
    __syncthreads();

    for (int it = 0; it < NS; it++) {
        int cur = it & 1;
        if (it+1 < NS) {
            int nxt = cur ^ 1;
#pragma unroll
            for (int j = 0; j < 2; j++) {
                uint4 H, L; split8(&rA[j*8], H, L);
                *(uint4*)&SAh[nxt*6144 + j*3072 + sidx] = H;
                *(uint4*)&SAl[nxt*6144 + j*3072 + sidx] = L;
                if (vsel == 0) *(uint4*)&SVh[nxt*2304 + j*1152 + vk*72 + vd0] = rV[j];
                else           *(uint4*)&SVl[nxt*2304 + j*1152 + vk*72 + vd0] = rV[j];
            }
            if (it+2 < NS) {
#pragma unroll
                for (int j = 0; j < 2; j++) {
                    int kst = (it+2)*2 + j;
                    *(float4*)&rA[j*8]   = __ldcs((const float4*)(attn + aoff + kst*16));
                    *(float4*)&rA[j*8+4] = __ldcs((const float4*)(attn + aoff + kst*16 + 4));
                    rV[j] = *(const uint4*)(Vsrc + voff + (size_t)kst*16*EMB);
                }
            }
        }
#pragma unroll
        for (int j = 0; j < 2; j++) {
            u32 obA = (u32)(cur*6144 + j*3072), obV = (u32)(cur*2304 + j*1152);
            u32 Ahf[2][4], Alf[2][4];
            load_afrag<2>(Ahf, Alf, pAh + 2u*obA, pAl + 2u*obA, wm*32, lane);
#pragma unroll
            for (int jp = 0; jp < 2; jp++) {
                int d = wn*32 + 16*jp + bdoff;
                u32 off = 2u * (obV + bk*72 + d);
                u32 bhf[4], blf[4];
                ldsm4t(bhf[0],bhf[1],bhf[2],bhf[3], pVh + off);
                ldsm4t(blf[0],blf[1],blf[2],blf[3], pVl + off);
#pragma unroll
                for (int i = 0; i < 2; i++) {
                    mma_bf16(acc[i][2*jp],   Ahf[i], bhf);
                    mma_bf16(acc[i][2*jp],   Ahf[i], blf);
                    mma_bf16(acc[i][2*jp],   Alf[i], bhf);
                    mma_bf16(acc[i][2*jp+1], Ahf[i], bhf+2);
                    mma_bf16(acc[i][2*jp+1], Ahf[i], blf+2);
                    mma_bf16(acc[i][2*jp+1], Alf[i], bhf+2);
                }
            }
        }
        __syncthreads();
    }

#pragma unroll
    for (int i=0;i<2;i++) {
        int row0 = bm*128 + wm*32 + 16*i + gid;
#pragma unroll
        for (int j=0;j<4;j++) {
            int col0 = wn*32 + 8*j + 2*tig;
            size_t o0 = (size_t)(b*SFULL + 1 + row0)*EMB + h*HD + col0;
            size_t o8 = (size_t)(b*SFULL + 9 + row0)*EMB + h*HD + col0;
            bf16 hh,ll; bf162 th, tl;
            split1(acc[i][j][0],hh,ll); th.x=hh; tl.x=ll;
            split1(acc[i][j][1],hh,ll); th.y=hh; tl.y=ll;
            *(bf162*)(g_Yh+o0)=th; *(bf162*)(g_Yl+o0)=tl;
            split1(acc[i][j][2],hh,ll); th.x=hh; tl.x=ll;
            split1(acc[i][j][3],hh,ll); th.y=hh; tl.y=ll;
            *(bf162*)(g_Yh+o8)=th; *(bf162*)(g_Yl+o8)=tl;
        }
    }
}
#define AV_SMEM ((12288*2 + 4608*2) * 2)

// ---------------- c projection (+ counter reset) ----------------
__global__ void cproj_kernel(const float* __restrict__ x,
                             const float* __restrict__ Wc,
                             const float* __restrict__ bc)
{
    int b = blockIdx.x;
    if (b == 0)
        for (int i = threadIdx.x; i < BH*8; i += blockDim.x) g_scnt[i] = 0;
    __shared__ float xs[EMB];
    for (int e = threadIdx.x; e < EMB; e += blockDim.x)
        xs[e] = x[(size_t)b * SFULL * EMB + e];
    __syncthreads();
    for (int j = threadIdx.x; j < EMB; j += blockDim.x) {
        const float* w = Wc + (size_t)j * EMB;
        float acc = bc[j];
        for (int e = 0; e < EMB; e++) acc += xs[e] * w[e];
        g_C[b * EMB + j] = acc;
    }
}

// ---------------- coefficients (from bf16 h+l) ----------------
__global__ __launch_bounds__(256) void coef_kernel()
{
    int gw = blockIdx.x * 8 + (threadIdx.x >> 5);
    int lane = threadIdx.x & 31;
    int q = gw & (SEQ - 1);
    int bh = gw >> 10;
    int b = bh / NH, h = bh % NH;
    const bf16* srcH = (blockIdx.y == 0) ? g_Qh : g_Kh;
    const bf16* srcL = (blockIdx.y == 0) ? g_Ql : g_Kl;
    size_t qo = (size_t)(b * SEQ + q) * EMB + h * HD;
    const float* cp = g_C + b * EMB + h * HD;
    float q0 = __bfloat162float(srcH[qo+lane]) + __bfloat162float(srcL[qo+lane]);
    float q1 = __bfloat162float(srcH[qo+lane+32]) + __bfloat162float(srcL[qo+lane+32]);
    float c0 = cp[lane], c1 = cp[lane + 32];
    float qn = q0*q0 + q1*q1;
    float cq = c0*q0 + c1*q1;
    float cn = c0*c0 + c1*c1;
#pragma unroll
    for (int o = 16; o; o >>= 1) {
        qn += __shfl_xor_sync(0xffffffffu, qn, o);
        cq += __shfl_xor_sync(0xffffffffu, cq, o);
        cn += __shfl_xor_sync(0xffffffffu, cn, o);
    }
    if (lane == 0) {
        float cn2 = fmaxf(cn, 1e-5f);
        if (blockIdx.y == 0) {
            float qn2 = fmaxf(qn, 1e-5f);
            g_coef[gw] = cq / (qn2 * sqrtf(64.0f * cn2));
        } else {
            g_ck[gw] = cq / sqrtf(64.0f * cn2);
        }
    }
}

// ---------------- CLS row (V from bf16 h+l) ----------------
__global__ void cls_kernel(const float* __restrict__ x)
{
    int bh = blockIdx.x;
    int b = bh / NH, h = bh % NH;
    int d = threadIdx.x;  // 64 threads
    __shared__ float cks[SEQ];
    for (int k = d; k < SEQ; k += 64) cks[k] = g_ck[bh * SEQ + k];
    __syncthreads();
    size_t vb = (size_t)b * SEQ * EMB + h * HD + d;
    float acc = 0.f;
#pragma unroll 8
    for (int k = 0; k < SEQ; k++) {
        float v = __bfloat162float(g_Vh[vb + (size_t)k * EMB])
                + __bfloat162float(g_Vl[vb + (size_t)k * EMB]);
        acc += cks[k] * v;
    }
    float cls = x[(size_t)b * SFULL * EMB + h * HD + d];
    float y = 0.5f * (cls + acc);
    size_t o = (size_t)b * SFULL * EMB + h * HD + d;
    bf16 hh, ll; split1(y, hh, ll);
    g_Yh[o] = hh; g_Yl[o] = ll;
}

// ---------------------------------------------------------------------------
extern "C" void kernel_launch(void* const* d_in, const int* in_sizes, int n_in,
                              void* d_out, int out_size)
{
    const float* x  = (const float*)d_in[0];
    const float* Wq = (const float*)d_in[1]; const float* bq = (const float*)d_in[2];
    const float* Wk = (const float*)d_in[3]; const float* bk = (const float*)d_in[4];
    const float* Wv = (const float*)d_in[5]; const float* bv = (const float*)d_in[6];
    const float* Wc = (const float*)d_in[7]; const float* bc = (const float*)d_in[8];
    const float* Wo = (const float*)d_in[9]; const float* bo = (const float*)d_in[10];

    float* out  = (float*)d_out;
    float* attn = out + (size_t)NB * SFULL * EMB;

    cudaFuncSetAttribute(score_tc, cudaFuncAttributeMaxDynamicSharedMemorySize, SCORE_SMEM);
    cudaFuncSetAttribute(av_tc, cudaFuncAttributeMaxDynamicSharedMemorySize, AV_SMEM);

    int nx4 = NB*SFULL*EMB/4;
    convert_all<<<dim3((nx4+255)/256, 5), 256>>>(x, Wq, Wk, Wv, Wo); // 1
    cproj_kernel<<<8, 256>>>(x, Wc, bc);                             // 2 (+ counter reset)
    qkv_tc<<<dim3(6, 64, 3), 256>>>(bq, bk, bv);                     // 3
    coef_kernel<<<dim3(12288, 2), 256>>>();                          // 4
    score_tc<<<dim3(8, 8, 96), 256, SCORE_SMEM>>>(attn);             // 5 (+ softmax)
    av_tc<<<dim3(8, 96), 256, AV_SMEM>>>(attn);                      // 6
    cls_kernel<<<96, 64>>>(x);                                       // 7
    out_tc<<<dim3(6, 65), 256>>>(bo, out);                           // 8
}